// round 9
// baseline (speedup 1.0000x reference)
#include <cuda_runtime.h>
#include <cuda_bf16.h>
#include <stdint.h>
#include <math.h>

// ---------------- problem constants ----------------
#define TT    2048
#define H     16
#define NOPE  128
#define ROPE  64
#define VDIM  128
#define RANK  512
#define QIN   1536
#define HID   7168
#define DQK   576
#define QFW   (H * (NOPE + ROPE))   // 3072

typedef __nv_bfloat16 bf16;

// fp32 intermediates
static __device__ float g_qf[(size_t)TT * QFW];
static __device__ float g_S [(size_t)H * TT * TT];

// bf16 hi/lo pairs
static __device__ bf16 g_q_h  [(size_t)TT * QIN],      g_q_l  [(size_t)TT * QIN];
static __device__ bf16 g_wq_h [(size_t)QFW * QIN],     g_wq_l [(size_t)QFW * QIN];
static __device__ bf16 g_qf_h [(size_t)TT * QFW],      g_qf_l [(size_t)TT * QFW];
static __device__ bf16 g_wuk_h[(size_t)H * RANK * NOPE], g_wuk_l[(size_t)H * RANK * NOPE];
static __device__ bf16 g_qc_h [(size_t)TT * H * DQK],  g_qc_l [(size_t)TT * H * DQK];
static __device__ bf16 g_kc_h [(size_t)TT * DQK],      g_kc_l [(size_t)TT * DQK];
static __device__ bf16 g_S_h  [(size_t)H * TT * TT],   g_S_l  [(size_t)H * TT * TT];
static __device__ bf16 g_kT_h [(size_t)RANK * TT],     g_kT_l [(size_t)RANK * TT];
static __device__ bf16 g_ol_h [(size_t)TT * H * RANK], g_ol_l [(size_t)TT * H * RANK];
static __device__ bf16 g_kvb_h[(size_t)H * 256 * RANK], g_kvb_l[(size_t)H * 256 * RANK];
static __device__ bf16 g_o_h  [(size_t)TT * H * VDIM], g_o_l  [(size_t)TT * H * VDIM];
static __device__ bf16 g_wo_h [(size_t)HID * H * VDIM], g_wo_l [(size_t)HID * H * VDIM];

// ---------------- ptx helpers ----------------
#define MMA_BF16(C, A, B0, B1)                                              \
    asm volatile(                                                           \
        "mma.sync.aligned.m16n8k16.row.col.f32.bf16.bf16.f32 "              \
        "{%0,%1,%2,%3},{%4,%5,%6,%7},{%8,%9},{%0,%1,%2,%3};\n"              \
        : "+f"(C[0]), "+f"(C[1]), "+f"(C[2]), "+f"(C[3])                    \
        : "r"(A[0]), "r"(A[1]), "r"(A[2]), "r"(A[3]), "r"(B0), "r"(B1));

#define LDSM_X4(R0, R1, R2, R3, ADDR)                                       \
    asm volatile("ldmatrix.sync.aligned.m8n8.x4.shared.b16 {%0,%1,%2,%3}, [%4];" \
        : "=r"(R0), "=r"(R1), "=r"(R2), "=r"(R3) : "r"(ADDR));

#define CP16(SM, G) asm volatile("cp.async.cg.shared.global [%0], [%1], 16;\n" :: "r"(SM), "l"(G))
#define CP_COMMIT   asm volatile("cp.async.commit_group;\n")
#define CP_WAIT0    asm volatile("cp.async.wait_group 0;\n")
#define CP_WAIT1    asm volatile("cp.async.wait_group 1;\n")

__device__ __forceinline__ void wr_pair(bf16* hi, bf16* lo, long long idx, float v) {
    bf16 h = __float2bfloat16(v);
    hi[idx] = h;
    lo[idx] = __float2bfloat16(v - __bfloat162float(h));
}

// smem: tile = 128 rows x 32 bf16 (64B/row), swizzle: byteoff(r,ch)=r*64+((ch^((r>>1)&3))<<4)
// 4 parts per stage (Ahi Alo Bhi Blo) = 32KB; 3 stages = 96KB/CTA; 2 CTAs/SM
#define KT       32
#define PART     8192
#define BUF_SZ   32768
#define SM_TOTAL 98304

// ---------------- cp.async bf16x3 tensor-core GEMM ----------------
// 128 threads, 4 warps, each warp computes a 64x64 tile of the 128x128 CTA tile.
__global__ __launch_bounds__(128, 2)
void gemm_cp(const bf16* __restrict__ Ahi, const bf16* __restrict__ Alo,
             const bf16* __restrict__ Bhi, const bf16* __restrict__ Blo,
             float* __restrict__ Cfp, bf16* __restrict__ Chi, bf16* __restrict__ Clo,
             int K, int sa, int sb, int sc,
             long long aBS, long long bBS, long long cBS,
             float alpha, int mode)
{
    extern __shared__ char sm[];

    const int m0 = blockIdx.y * 128;
    const int n0 = blockIdx.x * 128;
    if ((mode & 1) && n0 > m0) return;
    int Keff = K;
    if (mode & 2) { int kl = m0 + 128; if (kl < Keff) Keff = kl; }

    Ahi += (long long)blockIdx.z * aBS + (long long)m0 * sa;
    Alo += (long long)blockIdx.z * aBS + (long long)m0 * sa;
    Bhi += (long long)blockIdx.z * bBS + (long long)n0 * sb;
    Blo += (long long)blockIdx.z * bBS + (long long)n0 * sb;
    const long long cOff = (long long)blockIdx.z * cBS + (long long)m0 * sc + n0;

    const int tid  = threadIdx.x;
    const int lane = tid & 31;
    const int wid  = tid >> 5;
    const int warpM = (wid & 1) * 64;
    const int warpN = (wid >> 1) * 64;

    const uint32_t smBase = (uint32_t)__cvta_generic_to_shared(sm);

    float acc[4][8][4];
#pragma unroll
    for (int mi = 0; mi < 4; mi++)
#pragma unroll
        for (int ni = 0; ni < 8; ni++)
#pragma unroll
            for (int j = 0; j < 4; j++) acc[mi][ni][j] = 0.0f;

    // staging: 128 threads, one row (64B = 4 chunks) per part each
    auto issueTile = [&](int t) {
        const int kt = t * KT;
        const uint32_t sb0 = smBase + (t % 3) * BUF_SZ;
        const int row = tid;
        const int sw = (row >> 1) & 3;
        const bf16* srcs[4] = {
            Ahi + (long long)row * sa + kt,
            Alo + (long long)row * sa + kt,
            Bhi + (long long)row * sb + kt,
            Blo + (long long)row * sb + kt };
#pragma unroll
        for (int p = 0; p < 4; p++) {
            const uint32_t pb = sb0 + p * PART + row * 64;
#pragma unroll
            for (int ch = 0; ch < 4; ch++)
                CP16(pb + ((ch ^ sw) << 4), srcs[p] + ch * 8);
        }
    };

    const int nT = Keff / KT;   // >= 4 for all our shapes
    issueTile(0); CP_COMMIT;
    issueTile(1); CP_COMMIT;

    for (int t = 0; t < nT; t++) {
        if (t + 1 < nT) { CP_WAIT1; } else { CP_WAIT0; }
        __syncthreads();   // stage t visible to all; all warps done reading stage (t+2)%3's buffer

        const uint32_t aHi = smBase + (t % 3) * BUF_SZ;
        const uint32_t aLo = aHi + PART;
        const uint32_t bHi = aLo + PART;
        const uint32_t bLo = bHi + PART;

#pragma unroll
        for (int ks = 0; ks < 2; ks++) {
            uint32_t ah[4][4], al[4][4];
            {
                const int lr = lane & 15;
                const int lc = lane >> 4;
#pragma unroll
                for (int mi = 0; mi < 4; mi++) {
                    int r  = warpM + mi * 16 + lr;
                    int ch = 2 * ks + lc;
                    uint32_t off = r * 64 + ((ch ^ ((r >> 1) & 3)) << 4);
                    LDSM_X4(ah[mi][0], ah[mi][1], ah[mi][2], ah[mi][3], aHi + off);
                    LDSM_X4(al[mi][0], al[mi][1], al[mi][2], al[mi][3], aLo + off);
                }
            }
            const int bn = (lane & 7) + ((lane >> 4) << 3);
            const int bc = 2 * ks + ((lane >> 3) & 1);
#pragma unroll
            for (int p = 0; p < 4; p++) {
                int r = warpN + p * 16 + bn;
                uint32_t off = r * 64 + ((bc ^ ((r >> 1) & 3)) << 4);
                uint32_t bh0, bh1, bh2, bh3, bl0, bl1, bl2, bl3;
                LDSM_X4(bh0, bh1, bh2, bh3, bHi + off);
                LDSM_X4(bl0, bl1, bl2, bl3, bLo + off);
#pragma unroll
                for (int mi = 0; mi < 4; mi++) {
                    MMA_BF16(acc[mi][2*p],   ah[mi], bh0, bh1);
                    MMA_BF16(acc[mi][2*p],   ah[mi], bl0, bl1);
                    MMA_BF16(acc[mi][2*p],   al[mi], bh0, bh1);
                    MMA_BF16(acc[mi][2*p+1], ah[mi], bh2, bh3);
                    MMA_BF16(acc[mi][2*p+1], ah[mi], bl2, bl3);
                    MMA_BF16(acc[mi][2*p+1], al[mi], bh2, bh3);
                }
            }
        }

        if (t + 2 < nT) { issueTile(t + 2); CP_COMMIT; }
    }

    // ---- epilogue ----
    const int g   = lane >> 2;
    const int tig = lane & 3;
#pragma unroll
    for (int mi = 0; mi < 4; mi++)
#pragma unroll
        for (int ni = 0; ni < 8; ni++) {
            int r  = warpM + mi * 16 + g;
            int cc = warpN + ni * 8 + 2 * tig;
            float v0 = alpha * acc[mi][ni][0], v1 = alpha * acc[mi][ni][1];
            float v2 = alpha * acc[mi][ni][2], v3 = alpha * acc[mi][ni][3];
            long long i0 = cOff + (long long)r * sc + cc;
            long long i1 = cOff + (long long)(r + 8) * sc + cc;
            if (Cfp) {
                *(float2*)&Cfp[i0] = make_float2(v0, v1);
                *(float2*)&Cfp[i1] = make_float2(v2, v3);
            }
            if (Chi) {
                __nv_bfloat162 h2, l2;
                h2.x = __float2bfloat16(v0); h2.y = __float2bfloat16(v1);
                l2.x = __float2bfloat16(v0 - __bfloat162float(h2.x));
                l2.y = __float2bfloat16(v1 - __bfloat162float(h2.y));
                *(__nv_bfloat162*)&Chi[i0] = h2;
                *(__nv_bfloat162*)&Clo[i0] = l2;
                h2.x = __float2bfloat16(v2); h2.y = __float2bfloat16(v3);
                l2.x = __float2bfloat16(v2 - __bfloat162float(h2.x));
                l2.y = __float2bfloat16(v3 - __bfloat162float(h2.y));
                *(__nv_bfloat162*)&Chi[i1] = h2;
                *(__nv_bfloat162*)&Clo[i1] = l2;
            }
        }
}

// ---------------- conversion kernels ----------------
__global__ void cvt_pair(const float4* __restrict__ src,
                         __nv_bfloat162* __restrict__ hi, __nv_bfloat162* __restrict__ lo,
                         int n4)
{
    int i = blockIdx.x * 256 + threadIdx.x;
    if (i >= n4) return;
    float4 v = src[i];
    bf16 hx = __float2bfloat16(v.x), hy = __float2bfloat16(v.y);
    bf16 hz = __float2bfloat16(v.z), hw = __float2bfloat16(v.w);
    __nv_bfloat162 h0; h0.x = hx; h0.y = hy;
    __nv_bfloat162 h1; h1.x = hz; h1.y = hw;
    hi[2*i] = h0; hi[2*i+1] = h1;
    __nv_bfloat162 l0, l1;
    l0.x = __float2bfloat16(v.x - __bfloat162float(hx));
    l0.y = __float2bfloat16(v.y - __bfloat162float(hy));
    l1.x = __float2bfloat16(v.z - __bfloat162float(hz));
    l1.y = __float2bfloat16(v.w - __bfloat162float(hw));
    lo[2*i] = l0; lo[2*i+1] = l1;
}

// dst[q][p] = src[p][q], with batch strides
__global__ void tr_cvt(const float* __restrict__ src, bf16* __restrict__ hi, bf16* __restrict__ lo,
                       int P, int Q, long long srcBS, long long dstBS)
{
    __shared__ float t[32][33];
    const int p0 = blockIdx.y * 32, q0 = blockIdx.x * 32;
    const float* s = src + (long long)blockIdx.z * srcBS;
    t[threadIdx.y][threadIdx.x] = s[(long long)(p0 + threadIdx.y) * Q + q0 + threadIdx.x];
    __syncthreads();
    long long o = (long long)blockIdx.z * dstBS + (long long)(q0 + threadIdx.y) * P + p0 + threadIdx.x;
    wr_pair(hi, lo, o, t[threadIdx.x][threadIdx.y]);
}

// ---------------- RoPE + pack (writes bf16 pairs) ----------------
__global__ void rope_pack(const float* __restrict__ qf, const float* __restrict__ k_c,
                          const float* __restrict__ k_pe, const int* __restrict__ pos,
                          const float* __restrict__ cosc, const float* __restrict__ sinc,
                          float scale)
{
    int t = blockIdx.x;
    int p = pos[t];
    const float* cs = cosc + (long long)p * (ROPE / 2);
    const float* sn = sinc + (long long)p * (ROPE / 2);

    for (int i = threadIdx.x; i < RANK; i += blockDim.x)
        wr_pair(g_kc_h, g_kc_l, (long long)t * DQK + i, k_c[(long long)t * RANK + i]);

    for (int j = threadIdx.x; j < ROPE / 2; j += blockDim.x) {
        float x1 = k_pe[(long long)t * ROPE + j];
        float x2 = k_pe[(long long)t * ROPE + j + ROPE / 2];
        float c = cs[j], s = sn[j];
        wr_pair(g_kc_h, g_kc_l, (long long)t * DQK + RANK + j,            x1 * c - x2 * s);
        wr_pair(g_kc_h, g_kc_l, (long long)t * DQK + RANK + ROPE / 2 + j, x2 * c + x1 * s);
    }

    for (int idx = threadIdx.x; idx < H * (ROPE / 2); idx += blockDim.x) {
        int h = idx / (ROPE / 2);
        int j = idx % (ROPE / 2);
        float x1 = qf[(long long)t * QFW + h * (NOPE + ROPE) + NOPE + j];
        float x2 = qf[(long long)t * QFW + h * (NOPE + ROPE) + NOPE + ROPE / 2 + j];
        float c = cs[j], s = sn[j];
        long long base = ((long long)t * H + h) * DQK + RANK;
        wr_pair(g_qc_h, g_qc_l, base + j,            scale * (x1 * c - x2 * s));
        wr_pair(g_qc_h, g_qc_l, base + ROPE / 2 + j, scale * (x2 * c + x1 * s));
    }
}

// ---------------- causal softmax: fp32 in, bf16 pair out ----------------
__global__ __launch_bounds__(256)
void softmax_causal(const float* __restrict__ S, bf16* __restrict__ Ph, bf16* __restrict__ Pl,
                    const int* __restrict__ pos)
{
    const int t = blockIdx.x;
    const int h = blockIdx.y;
    const long long rb = ((long long)h * TT + t) * TT;
    const int pq = pos[t];
    const int limit = ((t >> 7) + 1) << 7;

    __shared__ float red[256];
    const int tid = threadIdx.x;

    float v[8];
    float m = -1e30f;
#pragma unroll
    for (int i = 0; i < 8; i++) {
        int s = tid + i * 256;
        v[i] = -1e30f;
        if (s < limit && pos[s] <= pq) v[i] = S[rb + s];
        m = fmaxf(m, v[i]);
    }
    red[tid] = m; __syncthreads();
    for (int w = 128; w > 0; w >>= 1) {
        if (tid < w) red[tid] = fmaxf(red[tid], red[tid + w]);
        __syncthreads();
    }
    m = red[0];
    __syncthreads();

    float sum = 0.0f;
#pragma unroll
    for (int i = 0; i < 8; i++) {
        v[i] = __expf(v[i] - m);
        sum += v[i];
    }
    red[tid] = sum; __syncthreads();
    for (int w = 128; w > 0; w >>= 1) {
        if (tid < w) red[tid] += red[tid + w];
        __syncthreads();
    }
    float inv = 1.0f / red[0];

#pragma unroll
    for (int i = 0; i < 8; i++) {
        int s = tid + i * 256;
        if (s < limit) wr_pair(Ph, Pl, rb + s, v[i] * inv);
    }
}

// ---------------- launch ----------------
extern "C" void kernel_launch(void* const* d_in, const int* in_sizes, int n_in,
                              void* d_out, int out_size)
{
    const float* q     = (const float*)d_in[0];
    const float* k_c   = (const float*)d_in[1];
    const float* k_pe  = (const float*)d_in[2];
    const int*   pos   = (const int*)  d_in[3];
    const float* wq    = (const float*)d_in[4];
    const float* kv_b  = (const float*)d_in[5];
    const float* wo    = (const float*)d_in[6];
    const float* cosc  = (const float*)d_in[7];
    const float* sinc  = (const float*)d_in[8];
    float* out = (float*)d_out;

    float *qf, *S;
    cudaGetSymbolAddress((void**)&qf, g_qf);
    cudaGetSymbolAddress((void**)&S,  g_S);
    bf16 *q_h,*q_l,*wq_h,*wq_l,*qf_h,*qf_l,*wuk_h,*wuk_l,*qc_h,*qc_l,*kc_h,*kc_l;
    bf16 *S_h,*S_l,*kT_h,*kT_l,*ol_h,*ol_l,*kvb_h,*kvb_l,*o_h,*o_l,*wo_h,*wo_l;
    cudaGetSymbolAddress((void**)&q_h,  g_q_h);  cudaGetSymbolAddress((void**)&q_l,  g_q_l);
    cudaGetSymbolAddress((void**)&wq_h, g_wq_h); cudaGetSymbolAddress((void**)&wq_l, g_wq_l);
    cudaGetSymbolAddress((void**)&qf_h, g_qf_h); cudaGetSymbolAddress((void**)&qf_l, g_qf_l);
    cudaGetSymbolAddress((void**)&wuk_h,g_wuk_h);cudaGetSymbolAddress((void**)&wuk_l,g_wuk_l);
    cudaGetSymbolAddress((void**)&qc_h, g_qc_h); cudaGetSymbolAddress((void**)&qc_l, g_qc_l);
    cudaGetSymbolAddress((void**)&kc_h, g_kc_h); cudaGetSymbolAddress((void**)&kc_l, g_kc_l);
    cudaGetSymbolAddress((void**)&S_h,  g_S_h);  cudaGetSymbolAddress((void**)&S_l,  g_S_l);
    cudaGetSymbolAddress((void**)&kT_h, g_kT_h); cudaGetSymbolAddress((void**)&kT_l, g_kT_l);
    cudaGetSymbolAddress((void**)&ol_h, g_ol_h); cudaGetSymbolAddress((void**)&ol_l, g_ol_l);
    cudaGetSymbolAddress((void**)&kvb_h,g_kvb_h);cudaGetSymbolAddress((void**)&kvb_l,g_kvb_l);
    cudaGetSymbolAddress((void**)&o_h,  g_o_h);  cudaGetSymbolAddress((void**)&o_l,  g_o_l);
    cudaGetSymbolAddress((void**)&wo_h, g_wo_h); cudaGetSymbolAddress((void**)&wo_l, g_wo_l);

    cudaFuncSetAttribute(gemm_cp, cudaFuncAttributeMaxDynamicSharedMemorySize, SM_TOTAL);

    const float scale = rsqrtf((float)(NOPE + ROPE));

    // ---- operand preconversion ----
    {
        int n4;
        n4 = TT * QIN / 4;
        cvt_pair<<<(n4 + 255) / 256, 256>>>((const float4*)q,  (__nv_bfloat162*)q_h,  (__nv_bfloat162*)q_l,  n4);
        n4 = QFW * QIN / 4;
        cvt_pair<<<(n4 + 255) / 256, 256>>>((const float4*)wq, (__nv_bfloat162*)wq_h, (__nv_bfloat162*)wq_l, n4);
        n4 = H * 256 * RANK / 4;
        cvt_pair<<<(n4 + 255) / 256, 256>>>((const float4*)kv_b, (__nv_bfloat162*)kvb_h, (__nv_bfloat162*)kvb_l, n4);
        n4 = HID * H * VDIM / 4;
        cvt_pair<<<(n4 + 255) / 256, 256>>>((const float4*)wo, (__nv_bfloat162*)wo_h, (__nv_bfloat162*)wo_l, n4);
        tr_cvt<<<dim3(RANK / 32, NOPE / 32, H), dim3(32, 32)>>>(
            kv_b, wuk_h, wuk_l, NOPE, RANK, (long long)256 * RANK, (long long)RANK * NOPE);
        tr_cvt<<<dim3(RANK / 32, TT / 32, 1), dim3(32, 32)>>>(
            k_c, kT_h, kT_l, TT, RANK, 0, 0);
    }

    // 1) qf = q @ wq^T : M=2048 N=3072 K=1536  (fp32 + bf16 pair out)
    gemm_cp<<<dim3(QFW / 128, TT / 128, 1), 128, SM_TOTAL>>>(
        q_h, q_l, wq_h, wq_l, qf, qf_h, qf_l,
        QIN, QIN, QIN, QFW, 0, 0, 0, 1.0f, 0);

    // 2) rope + pack
    rope_pack<<<TT, 256>>>(qf, k_c, k_pe, pos, cosc, sinc, scale);

    // 3) q_lat per head: M=2048 N=512 K=128 -> qcat pair cols 0..511, alpha=SCALE
    gemm_cp<<<dim3(RANK / 128, TT / 128, H), 128, SM_TOTAL>>>(
        qf_h, qf_l, wuk_h, wuk_l, nullptr, qc_h, qc_l,
        NOPE, QFW, NOPE, H * DQK,
        (long long)(NOPE + ROPE), (long long)RANK * NOPE, (long long)DQK, scale, 0);

    // 4) S_h = Qcat_h @ Kcat^T : M=2048 N=2048 K=576 (causal tile skip, fp32 out)
    gemm_cp<<<dim3(TT / 128, TT / 128, H), 128, SM_TOTAL>>>(
        qc_h, qc_l, kc_h, kc_l, S, nullptr, nullptr,
        DQK, H * DQK, DQK, TT,
        (long long)DQK, 0, (long long)TT * TT, 1.0f, 1);

    // 5) softmax -> bf16 pair probs
    softmax_causal<<<dim3(TT, H), 256>>>(S, S_h, S_l, pos);

    // 6) olat_h = P_h @ k_c : M=2048 N=512, K limited to m0+128
    gemm_cp<<<dim3(RANK / 128, TT / 128, H), 128, SM_TOTAL>>>(
        S_h, S_l, kT_h, kT_l, nullptr, ol_h, ol_l,
        TT, TT, TT, H * RANK,
        (long long)TT * TT, 0, (long long)RANK, 1.0f, 2);

    // 7) o_h = olat_h @ w_uv_h : M=2048 N=128 K=512
    gemm_cp<<<dim3(VDIM / 128, TT / 128, H), 128, SM_TOTAL>>>(
        ol_h, ol_l, kvb_h + (long long)NOPE * RANK, kvb_l + (long long)NOPE * RANK,
        nullptr, o_h, o_l,
        RANK, H * RANK, RANK, H * VDIM,
        (long long)RANK, (long long)256 * RANK, (long long)VDIM, 1.0f, 0);

    // 8) out = o @ wo^T : M=2048 N=7168 K=2048 (fp32 out)
    gemm_cp<<<dim3(HID / 128, TT / 128, 1), 128, SM_TOTAL>>>(
        o_h, o_l, wo_h, wo_l, out, nullptr, nullptr,
        H * VDIM, H * VDIM, H * VDIM, HID, 0, 0, 0, 1.0f, 0);
}

// round 10
// speedup vs baseline: 1.1686x; 1.1686x over previous
#include <cuda_runtime.h>
#include <cuda_bf16.h>
#include <stdint.h>
#include <math.h>

// ---------------- problem constants ----------------
#define TT    2048
#define H     16
#define NOPE  128
#define ROPE  64
#define VDIM  128
#define RANK  512
#define QIN   1536
#define HID   7168
#define DQK   576
#define QFW   (H * (NOPE + ROPE))   // 3072

typedef __nv_bfloat16 bf16;

// fp32 intermediates
static __device__ float g_qf[(size_t)TT * QFW];
static __device__ float g_S [(size_t)H * TT * TT];

// bf16 hi/lo pairs
static __device__ bf16 g_q_h  [(size_t)TT * QIN],      g_q_l  [(size_t)TT * QIN];
static __device__ bf16 g_wq_h [(size_t)QFW * QIN],     g_wq_l [(size_t)QFW * QIN];
static __device__ bf16 g_qf_h [(size_t)TT * QFW],      g_qf_l [(size_t)TT * QFW];
static __device__ bf16 g_wuk_h[(size_t)H * RANK * NOPE], g_wuk_l[(size_t)H * RANK * NOPE];
static __device__ bf16 g_qc_h [(size_t)TT * H * DQK],  g_qc_l [(size_t)TT * H * DQK];
static __device__ bf16 g_kc_h [(size_t)TT * DQK],      g_kc_l [(size_t)TT * DQK];
static __device__ bf16 g_S_h  [(size_t)H * TT * TT],   g_S_l  [(size_t)H * TT * TT];
static __device__ bf16 g_kT_h [(size_t)RANK * TT],     g_kT_l [(size_t)RANK * TT];
static __device__ bf16 g_ol_h [(size_t)TT * H * RANK], g_ol_l [(size_t)TT * H * RANK];
static __device__ bf16 g_kvb_h[(size_t)H * 256 * RANK], g_kvb_l[(size_t)H * 256 * RANK];
static __device__ bf16 g_o_h  [(size_t)TT * H * VDIM], g_o_l  [(size_t)TT * H * VDIM];
static __device__ bf16 g_wo_h [(size_t)HID * H * VDIM], g_wo_l [(size_t)HID * H * VDIM];

// ---------------- ptx helpers ----------------
#define MMA_BF16(C, A, B0, B1)                                              \
    asm volatile(                                                           \
        "mma.sync.aligned.m16n8k16.row.col.f32.bf16.bf16.f32 "              \
        "{%0,%1,%2,%3},{%4,%5,%6,%7},{%8,%9},{%0,%1,%2,%3};\n"              \
        : "+f"(C[0]), "+f"(C[1]), "+f"(C[2]), "+f"(C[3])                    \
        : "r"(A[0]), "r"(A[1]), "r"(A[2]), "r"(A[3]), "r"(B0), "r"(B1));

#define LDSM_X4(R0, R1, R2, R3, ADDR)                                       \
    asm volatile("ldmatrix.sync.aligned.m8n8.x4.shared.b16 {%0,%1,%2,%3}, [%4];" \
        : "=r"(R0), "=r"(R1), "=r"(R2), "=r"(R3) : "r"(ADDR));

#define CP16(SM, G) asm volatile("cp.async.cg.shared.global [%0], [%1], 16;\n" :: "r"(SM), "l"(G))
#define CP_COMMIT   asm volatile("cp.async.commit_group;\n")
#define CP_WAIT0    asm volatile("cp.async.wait_group 0;\n")
#define CP_WAIT1    asm volatile("cp.async.wait_group 1;\n")

__device__ __forceinline__ void wr_pair(bf16* hi, bf16* lo, long long idx, float v) {
    bf16 h = __float2bfloat16(v);
    hi[idx] = h;
    lo[idx] = __float2bfloat16(v - __bfloat162float(h));
}

// smem: tile = 128 rows x 32 bf16 (64B/row), swizzle: byteoff(r,ch)=r*64+((ch^((r>>1)&3))<<4)
// 4 parts per stage (Ahi Alo Bhi Blo) = 32KB; 3 stages = 96KB/CTA; 2 CTAs/SM
#define KT       32
#define PART     8192
#define BUF_SZ   32768
#define SM_TOTAL 98304

// ---------------- cp.async bf16x3 tensor-core GEMM (2 CTAs/SM, 3-stage) ----------------
__global__ __launch_bounds__(256, 2)
void gemm_cp(const bf16* __restrict__ Ahi, const bf16* __restrict__ Alo,
             const bf16* __restrict__ Bhi, const bf16* __restrict__ Blo,
             float* __restrict__ Cfp, bf16* __restrict__ Chi, bf16* __restrict__ Clo,
             int K, int sa, int sb, int sc,
             long long aBS, long long bBS, long long cBS,
             float alpha, int mode)
{
    extern __shared__ char sm[];

    const int m0 = blockIdx.y * 128;
    const int n0 = blockIdx.x * 128;
    if ((mode & 1) && n0 > m0) return;
    int Keff = K;
    if (mode & 2) { int kl = m0 + 128; if (kl < Keff) Keff = kl; }

    Ahi += (long long)blockIdx.z * aBS + (long long)m0 * sa;
    Alo += (long long)blockIdx.z * aBS + (long long)m0 * sa;
    Bhi += (long long)blockIdx.z * bBS + (long long)n0 * sb;
    Blo += (long long)blockIdx.z * bBS + (long long)n0 * sb;
    const long long cOff = (long long)blockIdx.z * cBS + (long long)m0 * sc + n0;

    const int tid  = threadIdx.x;
    const int lane = tid & 31;
    const int wid  = tid >> 5;
    const int warpM = (wid & 3) * 32;
    const int warpN = (wid >> 2) * 64;
    const int srow  = tid >> 1;          // staging row 0..127
    const int sch0  = (tid & 1) * 2;     // first of two 16B chunks (0..3)

    const uint32_t smBase = (uint32_t)__cvta_generic_to_shared(sm);

    float acc[2][8][4];
#pragma unroll
    for (int mi = 0; mi < 2; mi++)
#pragma unroll
        for (int ni = 0; ni < 8; ni++)
#pragma unroll
            for (int j = 0; j < 4; j++) acc[mi][ni][j] = 0.0f;

    auto issueTile = [&](int t) {
        const int kt = t * KT;
        const uint32_t sb0 = smBase + (t % 3) * BUF_SZ;
        const bf16* srcs[4] = {
            Ahi + (long long)srow * sa + kt,
            Alo + (long long)srow * sa + kt,
            Bhi + (long long)srow * sb + kt,
            Blo + (long long)srow * sb + kt };
        const int sw = (srow >> 1) & 3;
#pragma unroll
        for (int p = 0; p < 4; p++) {
            const uint32_t pb = sb0 + p * PART + srow * 64;
#pragma unroll
            for (int i = 0; i < 2; i++) {
                int ch = sch0 + i;
                CP16(pb + ((ch ^ sw) << 4), srcs[p] + ch * 8);
            }
        }
    };

    const int nT = Keff / KT;    // >= 4 for all shapes used
    issueTile(0); CP_COMMIT;
    issueTile(1); CP_COMMIT;

    for (int t = 0; t < nT; t++) {
        // ensure tile t is resident (t+1 / t+2 may still be in flight)
        if (t + 1 < nT) { CP_WAIT1; } else { CP_WAIT0; }
        __syncthreads();   // also guarantees all warps are done reading buffer (t+2)%3

        if (t + 2 < nT) { issueTile(t + 2); CP_COMMIT; }

        const uint32_t aHi = smBase + (t % 3) * BUF_SZ;
        const uint32_t aLo = aHi + PART;
        const uint32_t bHi = aLo + PART;
        const uint32_t bLo = bHi + PART;

#pragma unroll
        for (int ks = 0; ks < 2; ks++) {
            uint32_t ah[2][4], al[2][4];
            {
                const int lr = lane & 15;
                const int lc = lane >> 4;
#pragma unroll
                for (int mi = 0; mi < 2; mi++) {
                    int r  = warpM + mi * 16 + lr;
                    int ch = 2 * ks + lc;
                    uint32_t off = r * 64 + ((ch ^ ((r >> 1) & 3)) << 4);
                    LDSM_X4(ah[mi][0], ah[mi][1], ah[mi][2], ah[mi][3], aHi + off);
                    LDSM_X4(al[mi][0], al[mi][1], al[mi][2], al[mi][3], aLo + off);
                }
            }
            const int bn = (lane & 7) + ((lane >> 4) << 3);
            const int bc = 2 * ks + ((lane >> 3) & 1);
#pragma unroll
            for (int p = 0; p < 4; p++) {
                int r = warpN + p * 16 + bn;
                uint32_t off = r * 64 + ((bc ^ ((r >> 1) & 3)) << 4);
                uint32_t bh0, bh1, bh2, bh3, bl0, bl1, bl2, bl3;
                LDSM_X4(bh0, bh1, bh2, bh3, bHi + off);
                LDSM_X4(bl0, bl1, bl2, bl3, bLo + off);
#pragma unroll
                for (int mi = 0; mi < 2; mi++) {
                    MMA_BF16(acc[mi][2*p],   ah[mi], bh0, bh1);
                    MMA_BF16(acc[mi][2*p],   ah[mi], bl0, bl1);
                    MMA_BF16(acc[mi][2*p],   al[mi], bh0, bh1);
                    MMA_BF16(acc[mi][2*p+1], ah[mi], bh2, bh3);
                    MMA_BF16(acc[mi][2*p+1], ah[mi], bl2, bl3);
                    MMA_BF16(acc[mi][2*p+1], al[mi], bh2, bh3);
                }
            }
        }
    }

    // ---- epilogue ----
    const int g   = lane >> 2;
    const int tig = lane & 3;
#pragma unroll
    for (int mi = 0; mi < 2; mi++)
#pragma unroll
        for (int ni = 0; ni < 8; ni++) {
            int r  = warpM + mi * 16 + g;
            int cc = warpN + ni * 8 + 2 * tig;
            float v0 = alpha * acc[mi][ni][0], v1 = alpha * acc[mi][ni][1];
            float v2 = alpha * acc[mi][ni][2], v3 = alpha * acc[mi][ni][3];
            long long i0 = cOff + (long long)r * sc + cc;
            long long i1 = cOff + (long long)(r + 8) * sc + cc;
            if (Cfp) {
                *(float2*)&Cfp[i0] = make_float2(v0, v1);
                *(float2*)&Cfp[i1] = make_float2(v2, v3);
            }
            if (Chi) {
                __nv_bfloat162 h2, l2;
                h2.x = __float2bfloat16(v0); h2.y = __float2bfloat16(v1);
                l2.x = __float2bfloat16(v0 - __bfloat162float(h2.x));
                l2.y = __float2bfloat16(v1 - __bfloat162float(h2.y));
                *(__nv_bfloat162*)&Chi[i0] = h2;
                *(__nv_bfloat162*)&Clo[i0] = l2;
                h2.x = __float2bfloat16(v2); h2.y = __float2bfloat16(v3);
                l2.x = __float2bfloat16(v2 - __bfloat162float(h2.x));
                l2.y = __float2bfloat16(v3 - __bfloat162float(h2.y));
                *(__nv_bfloat162*)&Chi[i1] = h2;
                *(__nv_bfloat162*)&Clo[i1] = l2;
            }
        }
}

// ---------------- conversion kernels ----------------
__global__ void cvt_pair(const float4* __restrict__ src,
                         __nv_bfloat162* __restrict__ hi, __nv_bfloat162* __restrict__ lo,
                         int n4)
{
    int i = blockIdx.x * 256 + threadIdx.x;
    if (i >= n4) return;
    float4 v = src[i];
    bf16 hx = __float2bfloat16(v.x), hy = __float2bfloat16(v.y);
    bf16 hz = __float2bfloat16(v.z), hw = __float2bfloat16(v.w);
    __nv_bfloat162 h0; h0.x = hx; h0.y = hy;
    __nv_bfloat162 h1; h1.x = hz; h1.y = hw;
    hi[2*i] = h0; hi[2*i+1] = h1;
    __nv_bfloat162 l0, l1;
    l0.x = __float2bfloat16(v.x - __bfloat162float(hx));
    l0.y = __float2bfloat16(v.y - __bfloat162float(hy));
    l1.x = __float2bfloat16(v.z - __bfloat162float(hz));
    l1.y = __float2bfloat16(v.w - __bfloat162float(hw));
    lo[2*i] = l0; lo[2*i+1] = l1;
}

// dst[q][p] = src[p][q], with batch strides
__global__ void tr_cvt(const float* __restrict__ src, bf16* __restrict__ hi, bf16* __restrict__ lo,
                       int P, int Q, long long srcBS, long long dstBS)
{
    __shared__ float t[32][33];
    const int p0 = blockIdx.y * 32, q0 = blockIdx.x * 32;
    const float* s = src + (long long)blockIdx.z * srcBS;
    t[threadIdx.y][threadIdx.x] = s[(long long)(p0 + threadIdx.y) * Q + q0 + threadIdx.x];
    __syncthreads();
    long long o = (long long)blockIdx.z * dstBS + (long long)(q0 + threadIdx.y) * P + p0 + threadIdx.x;
    wr_pair(hi, lo, o, t[threadIdx.x][threadIdx.y]);
}

// ---------------- RoPE + pack (writes bf16 pairs) ----------------
__global__ void rope_pack(const float* __restrict__ qf, const float* __restrict__ k_c,
                          const float* __restrict__ k_pe, const int* __restrict__ pos,
                          const float* __restrict__ cosc, const float* __restrict__ sinc,
                          float scale)
{
    int t = blockIdx.x;
    int p = pos[t];
    const float* cs = cosc + (long long)p * (ROPE / 2);
    const float* sn = sinc + (long long)p * (ROPE / 2);

    for (int i = threadIdx.x; i < RANK; i += blockDim.x)
        wr_pair(g_kc_h, g_kc_l, (long long)t * DQK + i, k_c[(long long)t * RANK + i]);

    for (int j = threadIdx.x; j < ROPE / 2; j += blockDim.x) {
        float x1 = k_pe[(long long)t * ROPE + j];
        float x2 = k_pe[(long long)t * ROPE + j + ROPE / 2];
        float c = cs[j], s = sn[j];
        wr_pair(g_kc_h, g_kc_l, (long long)t * DQK + RANK + j,            x1 * c - x2 * s);
        wr_pair(g_kc_h, g_kc_l, (long long)t * DQK + RANK + ROPE / 2 + j, x2 * c + x1 * s);
    }

    for (int idx = threadIdx.x; idx < H * (ROPE / 2); idx += blockDim.x) {
        int h = idx / (ROPE / 2);
        int j = idx % (ROPE / 2);
        float x1 = qf[(long long)t * QFW + h * (NOPE + ROPE) + NOPE + j];
        float x2 = qf[(long long)t * QFW + h * (NOPE + ROPE) + NOPE + ROPE / 2 + j];
        float c = cs[j], s = sn[j];
        long long base = ((long long)t * H + h) * DQK + RANK;
        wr_pair(g_qc_h, g_qc_l, base + j,            scale * (x1 * c - x2 * s));
        wr_pair(g_qc_h, g_qc_l, base + ROPE / 2 + j, scale * (x2 * c + x1 * s));
    }
}

// ---------------- causal softmax: fp32 in, bf16 pair out ----------------
__global__ __launch_bounds__(256)
void softmax_causal(const float* __restrict__ S, bf16* __restrict__ Ph, bf16* __restrict__ Pl,
                    const int* __restrict__ pos)
{
    const int t = blockIdx.x;
    const int h = blockIdx.y;
    const long long rb = ((long long)h * TT + t) * TT;
    const int pq = pos[t];
    const int limit = ((t >> 7) + 1) << 7;

    __shared__ float red[256];
    const int tid = threadIdx.x;

    float v[8];
    float m = -1e30f;
#pragma unroll
    for (int i = 0; i < 8; i++) {
        int s = tid + i * 256;
        v[i] = -1e30f;
        if (s < limit && pos[s] <= pq) v[i] = S[rb + s];
        m = fmaxf(m, v[i]);
    }
    red[tid] = m; __syncthreads();
    for (int w = 128; w > 0; w >>= 1) {
        if (tid < w) red[tid] = fmaxf(red[tid], red[tid + w]);
        __syncthreads();
    }
    m = red[0];
    __syncthreads();

    float sum = 0.0f;
#pragma unroll
    for (int i = 0; i < 8; i++) {
        v[i] = __expf(v[i] - m);
        sum += v[i];
    }
    red[tid] = sum; __syncthreads();
    for (int w = 128; w > 0; w >>= 1) {
        if (tid < w) red[tid] += red[tid + w];
        __syncthreads();
    }
    float inv = 1.0f / red[0];

#pragma unroll
    for (int i = 0; i < 8; i++) {
        int s = tid + i * 256;
        if (s < limit) wr_pair(Ph, Pl, rb + s, v[i] * inv);
    }
}

// ---------------- launch ----------------
extern "C" void kernel_launch(void* const* d_in, const int* in_sizes, int n_in,
                              void* d_out, int out_size)
{
    const float* q     = (const float*)d_in[0];
    const float* k_c   = (const float*)d_in[1];
    const float* k_pe  = (const float*)d_in[2];
    const int*   pos   = (const int*)  d_in[3];
    const float* wq    = (const float*)d_in[4];
    const float* kv_b  = (const float*)d_in[5];
    const float* wo    = (const float*)d_in[6];
    const float* cosc  = (const float*)d_in[7];
    const float* sinc  = (const float*)d_in[8];
    float* out = (float*)d_out;

    float *qf, *S;
    cudaGetSymbolAddress((void**)&qf, g_qf);
    cudaGetSymbolAddress((void**)&S,  g_S);
    bf16 *q_h,*q_l,*wq_h,*wq_l,*qf_h,*qf_l,*wuk_h,*wuk_l,*qc_h,*qc_l,*kc_h,*kc_l;
    bf16 *S_h,*S_l,*kT_h,*kT_l,*ol_h,*ol_l,*kvb_h,*kvb_l,*o_h,*o_l,*wo_h,*wo_l;
    cudaGetSymbolAddress((void**)&q_h,  g_q_h);  cudaGetSymbolAddress((void**)&q_l,  g_q_l);
    cudaGetSymbolAddress((void**)&wq_h, g_wq_h); cudaGetSymbolAddress((void**)&wq_l, g_wq_l);
    cudaGetSymbolAddress((void**)&qf_h, g_qf_h); cudaGetSymbolAddress((void**)&qf_l, g_qf_l);
    cudaGetSymbolAddress((void**)&wuk_h,g_wuk_h);cudaGetSymbolAddress((void**)&wuk_l,g_wuk_l);
    cudaGetSymbolAddress((void**)&qc_h, g_qc_h); cudaGetSymbolAddress((void**)&qc_l, g_qc_l);
    cudaGetSymbolAddress((void**)&kc_h, g_kc_h); cudaGetSymbolAddress((void**)&kc_l, g_kc_l);
    cudaGetSymbolAddress((void**)&S_h,  g_S_h);  cudaGetSymbolAddress((void**)&S_l,  g_S_l);
    cudaGetSymbolAddress((void**)&kT_h, g_kT_h); cudaGetSymbolAddress((void**)&kT_l, g_kT_l);
    cudaGetSymbolAddress((void**)&ol_h, g_ol_h); cudaGetSymbolAddress((void**)&ol_l, g_ol_l);
    cudaGetSymbolAddress((void**)&kvb_h,g_kvb_h);cudaGetSymbolAddress((void**)&kvb_l,g_kvb_l);
    cudaGetSymbolAddress((void**)&o_h,  g_o_h);  cudaGetSymbolAddress((void**)&o_l,  g_o_l);
    cudaGetSymbolAddress((void**)&wo_h, g_wo_h); cudaGetSymbolAddress((void**)&wo_l, g_wo_l);

    cudaFuncSetAttribute(gemm_cp, cudaFuncAttributeMaxDynamicSharedMemorySize, SM_TOTAL);

    const float scale = rsqrtf((float)(NOPE + ROPE));

    // ---- operand preconversion ----
    {
        int n4;
        n4 = TT * QIN / 4;
        cvt_pair<<<(n4 + 255) / 256, 256>>>((const float4*)q,  (__nv_bfloat162*)q_h,  (__nv_bfloat162*)q_l,  n4);
        n4 = QFW * QIN / 4;
        cvt_pair<<<(n4 + 255) / 256, 256>>>((const float4*)wq, (__nv_bfloat162*)wq_h, (__nv_bfloat162*)wq_l, n4);
        n4 = H * 256 * RANK / 4;
        cvt_pair<<<(n4 + 255) / 256, 256>>>((const float4*)kv_b, (__nv_bfloat162*)kvb_h, (__nv_bfloat162*)kvb_l, n4);
        n4 = HID * H * VDIM / 4;
        cvt_pair<<<(n4 + 255) / 256, 256>>>((const float4*)wo, (__nv_bfloat162*)wo_h, (__nv_bfloat162*)wo_l, n4);
        tr_cvt<<<dim3(RANK / 32, NOPE / 32, H), dim3(32, 32)>>>(
            kv_b, wuk_h, wuk_l, NOPE, RANK, (long long)256 * RANK, (long long)RANK * NOPE);
        tr_cvt<<<dim3(RANK / 32, TT / 32, 1), dim3(32, 32)>>>(
            k_c, kT_h, kT_l, TT, RANK, 0, 0);
    }

    // 1) qf = q @ wq^T : M=2048 N=3072 K=1536  (fp32 + bf16 pair out)
    gemm_cp<<<dim3(QFW / 128, TT / 128, 1), 256, SM_TOTAL>>>(
        q_h, q_l, wq_h, wq_l, qf, qf_h, qf_l,
        QIN, QIN, QIN, QFW, 0, 0, 0, 1.0f, 0);

    // 2) rope + pack
    rope_pack<<<TT, 256>>>(qf, k_c, k_pe, pos, cosc, sinc, scale);

    // 3) q_lat per head: M=2048 N=512 K=128 -> qcat pair cols 0..511, alpha=SCALE
    gemm_cp<<<dim3(RANK / 128, TT / 128, H), 256, SM_TOTAL>>>(
        qf_h, qf_l, wuk_h, wuk_l, nullptr, qc_h, qc_l,
        NOPE, QFW, NOPE, H * DQK,
        (long long)(NOPE + ROPE), (long long)RANK * NOPE, (long long)DQK, scale, 0);

    // 4) S_h = Qcat_h @ Kcat^T : M=2048 N=2048 K=576 (causal tile skip, fp32 out)
    gemm_cp<<<dim3(TT / 128, TT / 128, H), 256, SM_TOTAL>>>(
        qc_h, qc_l, kc_h, kc_l, S, nullptr, nullptr,
        DQK, H * DQK, DQK, TT,
        (long long)DQK, 0, (long long)TT * TT, 1.0f, 1);

    // 5) softmax -> bf16 pair probs
    softmax_causal<<<dim3(TT, H), 256>>>(S, S_h, S_l, pos);

    // 6) olat_h = P_h @ k_c : M=2048 N=512, K limited to m0+128
    gemm_cp<<<dim3(RANK / 128, TT / 128, H), 256, SM_TOTAL>>>(
        S_h, S_l, kT_h, kT_l, nullptr, ol_h, ol_l,
        TT, TT, TT, H * RANK,
        (long long)TT * TT, 0, (long long)RANK, 1.0f, 2);

    // 7) o_h = olat_h @ w_uv_h : M=2048 N=128 K=512
    gemm_cp<<<dim3(VDIM / 128, TT / 128, H), 256, SM_TOTAL>>>(
        ol_h, ol_l, kvb_h + (long long)NOPE * RANK, kvb_l + (long long)NOPE * RANK,
        nullptr, o_h, o_l,
        RANK, H * RANK, RANK, H * VDIM,
        (long long)RANK, (long long)256 * RANK, (long long)VDIM, 1.0f, 0);

    // 8) out = o @ wo^T : M=2048 N=7168 K=2048 (fp32 out)
    gemm_cp<<<dim3(HID / 128, TT / 128, 1), 256, SM_TOTAL>>>(
        o_h, o_l, wo_h, wo_l, out, nullptr, nullptr,
        H * VDIM, H * VDIM, H * VDIM, HID, 0, 0, 0, 1.0f, 0);
}

// round 11
// speedup vs baseline: 1.3610x; 1.1647x over previous
#include <cuda_runtime.h>
#include <cuda_bf16.h>
#include <stdint.h>
#include <math.h>

// ---------------- problem constants ----------------
#define TT    2048
#define H     16
#define NOPE  128
#define ROPE  64
#define VDIM  128
#define RANK  512
#define QIN   1536
#define HID   7168
#define DQK   576
#define DS    192                    // per-head score dim (NOPE + ROPE)
#define QFW   (H * (NOPE + ROPE))    // 3072

typedef __nv_bfloat16 bf16;

// fp32 intermediates
static __device__ float g_qf[(size_t)TT * QFW];
static __device__ float g_S [(size_t)H * TT * TT];

// bf16 hi/lo pairs
static __device__ bf16 g_q_h  [(size_t)TT * QIN],      g_q_l  [(size_t)TT * QIN];
static __device__ bf16 g_wq_h [(size_t)QFW * QIN],     g_wq_l [(size_t)QFW * QIN];
static __device__ bf16 g_qf_h [(size_t)TT * QFW],      g_qf_l [(size_t)TT * QFW];   // == qc2 pairs
static __device__ bf16 g_kc_h [(size_t)TT * DQK],      g_kc_l [(size_t)TT * DQK];   // k_c pairs (cols 0..511 used)
static __device__ bf16 g_kc2_h[(size_t)H * TT * DS],   g_kc2_l[(size_t)H * TT * DS]; // [k_up | k_pe_r] per head
static __device__ bf16 g_S_h  [(size_t)H * TT * TT],   g_S_l  [(size_t)H * TT * TT];
static __device__ bf16 g_kT_h [(size_t)RANK * TT],     g_kT_l [(size_t)RANK * TT];
static __device__ bf16 g_ol_h [(size_t)TT * H * RANK], g_ol_l [(size_t)TT * H * RANK];
static __device__ bf16 g_kvb_h[(size_t)H * 256 * RANK], g_kvb_l[(size_t)H * 256 * RANK];
static __device__ bf16 g_o_h  [(size_t)TT * H * VDIM], g_o_l  [(size_t)TT * H * VDIM];
static __device__ bf16 g_wo_h [(size_t)HID * H * VDIM], g_wo_l [(size_t)HID * H * VDIM];

// ---------------- ptx helpers ----------------
#define MMA_BF16(C, A, B0, B1)                                              \
    asm volatile(                                                           \
        "mma.sync.aligned.m16n8k16.row.col.f32.bf16.bf16.f32 "              \
        "{%0,%1,%2,%3},{%4,%5,%6,%7},{%8,%9},{%0,%1,%2,%3};\n"              \
        : "+f"(C[0]), "+f"(C[1]), "+f"(C[2]), "+f"(C[3])                    \
        : "r"(A[0]), "r"(A[1]), "r"(A[2]), "r"(A[3]), "r"(B0), "r"(B1));

#define LDSM_X4(R0, R1, R2, R3, ADDR)                                       \
    asm volatile("ldmatrix.sync.aligned.m8n8.x4.shared.b16 {%0,%1,%2,%3}, [%4];" \
        : "=r"(R0), "=r"(R1), "=r"(R2), "=r"(R3) : "r"(ADDR));

#define CP16(SM, G) asm volatile("cp.async.cg.shared.global [%0], [%1], 16;\n" :: "r"(SM), "l"(G))
#define CP_COMMIT   asm volatile("cp.async.commit_group;\n")
#define CP_WAIT0    asm volatile("cp.async.wait_group 0;\n")
#define CP_WAIT1    asm volatile("cp.async.wait_group 1;\n")

__device__ __forceinline__ void wr_pair(bf16* hi, bf16* lo, long long idx, float v) {
    bf16 h = __float2bfloat16(v);
    hi[idx] = h;
    lo[idx] = __float2bfloat16(v - __bfloat162float(h));
}

// smem: tile = 128 rows x 32 bf16 (64B/row), swizzle: byteoff(r,ch)=r*64+((ch^((r>>1)&3))<<4)
#define KT       32
#define PART     8192
#define BUF_SZ   32768
#define SM_TOTAL 98304

// ---------------- cp.async bf16x3 tensor-core GEMM (2 CTAs/SM, 3-stage) ----------------
__global__ __launch_bounds__(256, 2)
void gemm_cp(const bf16* __restrict__ Ahi, const bf16* __restrict__ Alo,
             const bf16* __restrict__ Bhi, const bf16* __restrict__ Blo,
             float* __restrict__ Cfp, bf16* __restrict__ Chi, bf16* __restrict__ Clo,
             int K, int sa, int sb, int sc,
             long long aBS, long long bBS, long long cBS,
             float alpha, int mode)
{
    extern __shared__ char sm[];

    const int m0 = blockIdx.y * 128;
    const int n0 = blockIdx.x * 128;
    if ((mode & 1) && n0 > m0) return;
    int Keff = K;
    if (mode & 2) { int kl = m0 + 128; if (kl < Keff) Keff = kl; }

    Ahi += (long long)blockIdx.z * aBS + (long long)m0 * sa;
    Alo += (long long)blockIdx.z * aBS + (long long)m0 * sa;
    Bhi += (long long)blockIdx.z * bBS + (long long)n0 * sb;
    Blo += (long long)blockIdx.z * bBS + (long long)n0 * sb;
    const long long cOff = (long long)blockIdx.z * cBS + (long long)m0 * sc + n0;

    const int tid  = threadIdx.x;
    const int lane = tid & 31;
    const int wid  = tid >> 5;
    const int warpM = (wid & 3) * 32;
    const int warpN = (wid >> 2) * 64;
    const int srow  = tid >> 1;
    const int sch0  = (tid & 1) * 2;

    const uint32_t smBase = (uint32_t)__cvta_generic_to_shared(sm);

    float acc[2][8][4];
#pragma unroll
    for (int mi = 0; mi < 2; mi++)
#pragma unroll
        for (int ni = 0; ni < 8; ni++)
#pragma unroll
            for (int j = 0; j < 4; j++) acc[mi][ni][j] = 0.0f;

    auto issueTile = [&](int t) {
        const int kt = t * KT;
        const uint32_t sb0 = smBase + (t % 3) * BUF_SZ;
        const bf16* srcs[4] = {
            Ahi + (long long)srow * sa + kt,
            Alo + (long long)srow * sa + kt,
            Bhi + (long long)srow * sb + kt,
            Blo + (long long)srow * sb + kt };
        const int sw = (srow >> 1) & 3;
#pragma unroll
        for (int p = 0; p < 4; p++) {
            const uint32_t pb = sb0 + p * PART + srow * 64;
#pragma unroll
            for (int i = 0; i < 2; i++) {
                int ch = sch0 + i;
                CP16(pb + ((ch ^ sw) << 4), srcs[p] + ch * 8);
            }
        }
    };

    const int nT = Keff / KT;
    issueTile(0); CP_COMMIT;
    issueTile(1); CP_COMMIT;

    for (int t = 0; t < nT; t++) {
        if (t + 1 < nT) { CP_WAIT1; } else { CP_WAIT0; }
        __syncthreads();

        if (t + 2 < nT) { issueTile(t + 2); CP_COMMIT; }

        const uint32_t aHi = smBase + (t % 3) * BUF_SZ;
        const uint32_t aLo = aHi + PART;
        const uint32_t bHi = aLo + PART;
        const uint32_t bLo = bHi + PART;

#pragma unroll
        for (int ks = 0; ks < 2; ks++) {
            uint32_t ah[2][4], al[2][4];
            {
                const int lr = lane & 15;
                const int lc = lane >> 4;
#pragma unroll
                for (int mi = 0; mi < 2; mi++) {
                    int r  = warpM + mi * 16 + lr;
                    int ch = 2 * ks + lc;
                    uint32_t off = r * 64 + ((ch ^ ((r >> 1) & 3)) << 4);
                    LDSM_X4(ah[mi][0], ah[mi][1], ah[mi][2], ah[mi][3], aHi + off);
                    LDSM_X4(al[mi][0], al[mi][1], al[mi][2], al[mi][3], aLo + off);
                }
            }
            const int bn = (lane & 7) + ((lane >> 4) << 3);
            const int bc = 2 * ks + ((lane >> 3) & 1);
#pragma unroll
            for (int p = 0; p < 4; p++) {
                int r = warpN + p * 16 + bn;
                uint32_t off = r * 64 + ((bc ^ ((r >> 1) & 3)) << 4);
                uint32_t bh0, bh1, bh2, bh3, bl0, bl1, bl2, bl3;
                LDSM_X4(bh0, bh1, bh2, bh3, bHi + off);
                LDSM_X4(bl0, bl1, bl2, bl3, bLo + off);
#pragma unroll
                for (int mi = 0; mi < 2; mi++) {
                    MMA_BF16(acc[mi][2*p],   ah[mi], bh0, bh1);
                    MMA_BF16(acc[mi][2*p],   ah[mi], bl0, bl1);
                    MMA_BF16(acc[mi][2*p],   al[mi], bh0, bh1);
                    MMA_BF16(acc[mi][2*p+1], ah[mi], bh2, bh3);
                    MMA_BF16(acc[mi][2*p+1], ah[mi], bl2, bl3);
                    MMA_BF16(acc[mi][2*p+1], al[mi], bh2, bh3);
                }
            }
        }
    }

    // ---- epilogue ----
    const int g   = lane >> 2;
    const int tig = lane & 3;
#pragma unroll
    for (int mi = 0; mi < 2; mi++)
#pragma unroll
        for (int ni = 0; ni < 8; ni++) {
            int r  = warpM + mi * 16 + g;
            int cc = warpN + ni * 8 + 2 * tig;
            float v0 = alpha * acc[mi][ni][0], v1 = alpha * acc[mi][ni][1];
            float v2 = alpha * acc[mi][ni][2], v3 = alpha * acc[mi][ni][3];
            long long i0 = cOff + (long long)r * sc + cc;
            long long i1 = cOff + (long long)(r + 8) * sc + cc;
            if (Cfp) {
                *(float2*)&Cfp[i0] = make_float2(v0, v1);
                *(float2*)&Cfp[i1] = make_float2(v2, v3);
            }
            if (Chi) {
                __nv_bfloat162 h2, l2;
                h2.x = __float2bfloat16(v0); h2.y = __float2bfloat16(v1);
                l2.x = __float2bfloat16(v0 - __bfloat162float(h2.x));
                l2.y = __float2bfloat16(v1 - __bfloat162float(h2.y));
                *(__nv_bfloat162*)&Chi[i0] = h2;
                *(__nv_bfloat162*)&Clo[i0] = l2;
                h2.x = __float2bfloat16(v2); h2.y = __float2bfloat16(v3);
                l2.x = __float2bfloat16(v2 - __bfloat162float(h2.x));
                l2.y = __float2bfloat16(v3 - __bfloat162float(h2.y));
                *(__nv_bfloat162*)&Chi[i1] = h2;
                *(__nv_bfloat162*)&Clo[i1] = l2;
            }
        }
}

// ---------------- conversion kernels ----------------
__global__ void cvt_pair(const float4* __restrict__ src,
                         __nv_bfloat162* __restrict__ hi, __nv_bfloat162* __restrict__ lo,
                         int n4)
{
    int i = blockIdx.x * 256 + threadIdx.x;
    if (i >= n4) return;
    float4 v = src[i];
    bf16 hx = __float2bfloat16(v.x), hy = __float2bfloat16(v.y);
    bf16 hz = __float2bfloat16(v.z), hw = __float2bfloat16(v.w);
    __nv_bfloat162 h0; h0.x = hx; h0.y = hy;
    __nv_bfloat162 h1; h1.x = hz; h1.y = hw;
    hi[2*i] = h0; hi[2*i+1] = h1;
    __nv_bfloat162 l0, l1;
    l0.x = __float2bfloat16(v.x - __bfloat162float(hx));
    l0.y = __float2bfloat16(v.y - __bfloat162float(hy));
    l1.x = __float2bfloat16(v.z - __bfloat162float(hz));
    l1.y = __float2bfloat16(v.w - __bfloat162float(hw));
    lo[2*i] = l0; lo[2*i+1] = l1;
}

// dst[q][p] = src[p][q]
__global__ void tr_cvt(const float* __restrict__ src, bf16* __restrict__ hi, bf16* __restrict__ lo,
                       int P, int Q, long long srcBS, long long dstBS)
{
    __shared__ float t[32][33];
    const int p0 = blockIdx.y * 32, q0 = blockIdx.x * 32;
    const float* s = src + (long long)blockIdx.z * srcBS;
    t[threadIdx.y][threadIdx.x] = s[(long long)(p0 + threadIdx.y) * Q + q0 + threadIdx.x];
    __syncthreads();
    long long o = (long long)blockIdx.z * dstBS + (long long)(q0 + threadIdx.y) * P + p0 + threadIdx.x;
    wr_pair(hi, lo, o, t[threadIdx.x][threadIdx.y]);
}

// ---------------- RoPE + pack ----------------
// - k_c pairs into g_kc (row stride DQK, cols 0..511) for the k_up GEMM A operand
// - roped k_pe pairs into kc2[h][t][128..191] for ALL heads
// - roped q_pe pairs in-place into qf pairs (cols h*192+128..191); SCALE applied in softmax
__global__ void rope_pack(const float* __restrict__ qf, const float* __restrict__ k_c,
                          const float* __restrict__ k_pe, const int* __restrict__ pos,
                          const float* __restrict__ cosc, const float* __restrict__ sinc)
{
    int t = blockIdx.x;
    int p = pos[t];
    const float* cs = cosc + (long long)p * (ROPE / 2);
    const float* sn = sinc + (long long)p * (ROPE / 2);

    for (int i = threadIdx.x; i < RANK; i += blockDim.x)
        wr_pair(g_kc_h, g_kc_l, (long long)t * DQK + i, k_c[(long long)t * RANK + i]);

    for (int j = threadIdx.x; j < ROPE / 2; j += blockDim.x) {
        float x1 = k_pe[(long long)t * ROPE + j];
        float x2 = k_pe[(long long)t * ROPE + j + ROPE / 2];
        float c = cs[j], s = sn[j];
        float r1 = x1 * c - x2 * s;
        float r2 = x2 * c + x1 * s;
        bf16 h1 = __float2bfloat16(r1), l1 = __float2bfloat16(r1 - __bfloat162float(h1));
        bf16 h2 = __float2bfloat16(r2), l2 = __float2bfloat16(r2 - __bfloat162float(h2));
#pragma unroll
        for (int h = 0; h < H; h++) {
            long long base = ((long long)h * TT + t) * DS + NOPE;
            g_kc2_h[base + j] = h1; g_kc2_l[base + j] = l1;
            g_kc2_h[base + ROPE / 2 + j] = h2; g_kc2_l[base + ROPE / 2 + j] = l2;
        }
    }

    for (int idx = threadIdx.x; idx < H * (ROPE / 2); idx += blockDim.x) {
        int h = idx / (ROPE / 2);
        int j = idx % (ROPE / 2);
        long long qb = (long long)t * QFW + h * DS + NOPE;
        float x1 = qf[qb + j];
        float x2 = qf[qb + ROPE / 2 + j];
        float c = cs[j], s = sn[j];
        wr_pair(g_qf_h, g_qf_l, qb + j,            x1 * c - x2 * s);
        wr_pair(g_qf_h, g_qf_l, qb + ROPE / 2 + j, x2 * c + x1 * s);
    }
}

// ---------------- causal softmax: fp32 in (scaled on load), bf16 pair out ----------------
__global__ __launch_bounds__(256)
void softmax_causal(const float* __restrict__ S, bf16* __restrict__ Ph, bf16* __restrict__ Pl,
                    const int* __restrict__ pos, float scale)
{
    const int t = blockIdx.x;
    const int h = blockIdx.y;
    const long long rb = ((long long)h * TT + t) * TT;
    const int pq = pos[t];
    const int limit = ((t >> 7) + 1) << 7;

    __shared__ float red[256];
    const int tid = threadIdx.x;

    float v[8];
    float m = -1e30f;
#pragma unroll
    for (int i = 0; i < 8; i++) {
        int s = tid + i * 256;
        v[i] = -1e30f;
        if (s < limit && pos[s] <= pq) v[i] = S[rb + s] * scale;
        m = fmaxf(m, v[i]);
    }
    red[tid] = m; __syncthreads();
    for (int w = 128; w > 0; w >>= 1) {
        if (tid < w) red[tid] = fmaxf(red[tid], red[tid + w]);
        __syncthreads();
    }
    m = red[0];
    __syncthreads();

    float sum = 0.0f;
#pragma unroll
    for (int i = 0; i < 8; i++) {
        v[i] = __expf(v[i] - m);
        sum += v[i];
    }
    red[tid] = sum; __syncthreads();
    for (int w = 128; w > 0; w >>= 1) {
        if (tid < w) red[tid] += red[tid + w];
        __syncthreads();
    }
    float inv = 1.0f / red[0];

#pragma unroll
    for (int i = 0; i < 8; i++) {
        int s = tid + i * 256;
        if (s < limit) wr_pair(Ph, Pl, rb + s, v[i] * inv);
    }
}

// ---------------- launch ----------------
extern "C" void kernel_launch(void* const* d_in, const int* in_sizes, int n_in,
                              void* d_out, int out_size)
{
    const float* q     = (const float*)d_in[0];
    const float* k_c   = (const float*)d_in[1];
    const float* k_pe  = (const float*)d_in[2];
    const int*   pos   = (const int*)  d_in[3];
    const float* wq    = (const float*)d_in[4];
    const float* kv_b  = (const float*)d_in[5];
    const float* wo    = (const float*)d_in[6];
    const float* cosc  = (const float*)d_in[7];
    const float* sinc  = (const float*)d_in[8];
    float* out = (float*)d_out;

    float *qf, *S;
    cudaGetSymbolAddress((void**)&qf, g_qf);
    cudaGetSymbolAddress((void**)&S,  g_S);
    bf16 *q_h,*q_l,*wq_h,*wq_l,*qf_h,*qf_l,*kc_h,*kc_l,*kc2_h,*kc2_l;
    bf16 *S_h,*S_l,*kT_h,*kT_l,*ol_h,*ol_l,*kvb_h,*kvb_l,*o_h,*o_l,*wo_h,*wo_l;
    cudaGetSymbolAddress((void**)&q_h,  g_q_h);  cudaGetSymbolAddress((void**)&q_l,  g_q_l);
    cudaGetSymbolAddress((void**)&wq_h, g_wq_h); cudaGetSymbolAddress((void**)&wq_l, g_wq_l);
    cudaGetSymbolAddress((void**)&qf_h, g_qf_h); cudaGetSymbolAddress((void**)&qf_l, g_qf_l);
    cudaGetSymbolAddress((void**)&kc_h, g_kc_h); cudaGetSymbolAddress((void**)&kc_l, g_kc_l);
    cudaGetSymbolAddress((void**)&kc2_h,g_kc2_h);cudaGetSymbolAddress((void**)&kc2_l,g_kc2_l);
    cudaGetSymbolAddress((void**)&S_h,  g_S_h);  cudaGetSymbolAddress((void**)&S_l,  g_S_l);
    cudaGetSymbolAddress((void**)&kT_h, g_kT_h); cudaGetSymbolAddress((void**)&kT_l, g_kT_l);
    cudaGetSymbolAddress((void**)&ol_h, g_ol_h); cudaGetSymbolAddress((void**)&ol_l, g_ol_l);
    cudaGetSymbolAddress((void**)&kvb_h,g_kvb_h);cudaGetSymbolAddress((void**)&kvb_l,g_kvb_l);
    cudaGetSymbolAddress((void**)&o_h,  g_o_h);  cudaGetSymbolAddress((void**)&o_l,  g_o_l);
    cudaGetSymbolAddress((void**)&wo_h, g_wo_h); cudaGetSymbolAddress((void**)&wo_l, g_wo_l);

    cudaFuncSetAttribute(gemm_cp, cudaFuncAttributeMaxDynamicSharedMemorySize, SM_TOTAL);

    const float scale = rsqrtf((float)(NOPE + ROPE));

    // ---- operand preconversion ----
    {
        int n4;
        n4 = TT * QIN / 4;
        cvt_pair<<<(n4 + 255) / 256, 256>>>((const float4*)q,  (__nv_bfloat162*)q_h,  (__nv_bfloat162*)q_l,  n4);
        n4 = QFW * QIN / 4;
        cvt_pair<<<(n4 + 255) / 256, 256>>>((const float4*)wq, (__nv_bfloat162*)wq_h, (__nv_bfloat162*)wq_l, n4);
        n4 = H * 256 * RANK / 4;
        cvt_pair<<<(n4 + 255) / 256, 256>>>((const float4*)kv_b, (__nv_bfloat162*)kvb_h, (__nv_bfloat162*)kvb_l, n4);
        n4 = HID * H * VDIM / 4;
        cvt_pair<<<(n4 + 255) / 256, 256>>>((const float4*)wo, (__nv_bfloat162*)wo_h, (__nv_bfloat162*)wo_l, n4);
        // kcT[r][s] = k_c[s][r]  (B operand of GEMM6)
        tr_cvt<<<dim3(RANK / 32, TT / 32, 1), dim3(32, 32)>>>(
            k_c, kT_h, kT_l, TT, RANK, 0, 0);
    }

    // 1) qf = q @ wq^T : M=2048 N=3072 K=1536  (fp32 qf + pairs -> qc2 layout)
    gemm_cp<<<dim3(QFW / 128, TT / 128, 1), 256, SM_TOTAL>>>(
        q_h, q_l, wq_h, wq_l, qf, qf_h, qf_l,
        QIN, QIN, QIN, QFW, 0, 0, 0, 1.0f, 0);

    // 2) rope + pack (k_c pairs, kc2 rope cols for all heads, qc2 rope cols in-place)
    rope_pack<<<TT, 256>>>(qf, k_c, k_pe, pos, cosc, sinc);

    // 3) k_up_h = k_c @ w_uk_h : M=2048 N=128 K=512 -> kc2[h][:,0:128] pairs
    //    B = kv_b rows 0..127 of head h (k-contiguous, no transpose needed)
    gemm_cp<<<dim3(1, TT / 128, H), 256, SM_TOTAL>>>(
        kc_h, kc_l, kvb_h, kvb_l, nullptr, kc2_h, kc2_l,
        RANK, DQK, RANK, DS,
        0, (long long)256 * RANK, (long long)TT * DS, 1.0f, 0);

    // 4) S_h = Qc2_h @ Kc2_h^T : M=2048 N=2048 K=192 (causal tile skip, fp32 out)
    gemm_cp<<<dim3(TT / 128, TT / 128, H), 256, SM_TOTAL>>>(
        qf_h, qf_l, kc2_h, kc2_l, S, nullptr, nullptr,
        DS, QFW, DS, TT,
        (long long)DS, (long long)TT * DS, (long long)TT * TT, 1.0f, 1);

    // 5) softmax (SCALE applied on load) -> bf16 pair probs
    softmax_causal<<<dim3(TT, H), 256>>>(S, S_h, S_l, pos, scale);

    // 6) olat_h = P_h @ k_c : M=2048 N=512, K limited to m0+128
    gemm_cp<<<dim3(RANK / 128, TT / 128, H), 256, SM_TOTAL>>>(
        S_h, S_l, kT_h, kT_l, nullptr, ol_h, ol_l,
        TT, TT, TT, H * RANK,
        (long long)TT * TT, 0, (long long)RANK, 1.0f, 2);

    // 7) o_h = olat_h @ w_uv_h : M=2048 N=128 K=512
    gemm_cp<<<dim3(VDIM / 128, TT / 128, H), 256, SM_TOTAL>>>(
        ol_h, ol_l, kvb_h + (long long)NOPE * RANK, kvb_l + (long long)NOPE * RANK,
        nullptr, o_h, o_l,
        RANK, H * RANK, RANK, H * VDIM,
        (long long)RANK, (long long)256 * RANK, (long long)VDIM, 1.0f, 0);

    // 8) out = o @ wo^T : M=2048 N=7168 K=2048 (fp32 out)
    gemm_cp<<<dim3(HID / 128, TT / 128, 1), 256, SM_TOTAL>>>(
        o_h, o_l, wo_h, wo_l, out, nullptr, nullptr,
        H * VDIM, H * VDIM, H * VDIM, HID, 0, 0, 0, 1.0f, 0);
}

// round 12
// speedup vs baseline: 1.4209x; 1.0440x over previous
#include <cuda_runtime.h>
#include <cuda_bf16.h>
#include <cuda_fp16.h>
#include <stdint.h>
#include <math.h>

// ---------------- problem constants ----------------
#define TT    2048
#define H     16
#define NOPE  128
#define ROPE  64
#define VDIM  128
#define RANK  512
#define QIN   1536
#define HID   7168
#define DQK   576
#define DS    192
#define QFW   (H * (NOPE + ROPE))   // 3072

typedef __nv_bfloat16 bf16;

// fp32 intermediates
static __device__ float g_qf[(size_t)TT * QFW];

// bf16 hi/lo pairs (score path: bf16x3)
static __device__ bf16 g_q_h  [(size_t)TT * QIN],      g_q_l  [(size_t)TT * QIN];
static __device__ bf16 g_wq_h [(size_t)QFW * QIN],     g_wq_l [(size_t)QFW * QIN];
static __device__ bf16 g_qf_h [(size_t)TT * QFW],      g_qf_l [(size_t)TT * QFW];
static __device__ bf16 g_kc_h [(size_t)TT * DQK],      g_kc_l [(size_t)TT * DQK];
static __device__ bf16 g_kc2_h[(size_t)H * TT * DS],   g_kc2_l[(size_t)H * TT * DS];
static __device__ bf16 g_kvb_h[(size_t)H * 256 * RANK], g_kvb_l[(size_t)H * 256 * RANK];
static __device__ bf16 g_ol_h [(size_t)TT * H * RANK], g_ol_l [(size_t)TT * H * RANK];

// fp16 operands (value path: f16x2)
static __device__ __half g_Sp_h[(size_t)H * TT * TT], g_Sp_l[(size_t)H * TT * TT];
static __device__ __half g_kT16[(size_t)RANK * TT];
static __device__ __half g_o_h [(size_t)TT * H * VDIM], g_o_l [(size_t)TT * H * VDIM];
static __device__ __half g_wo16[(size_t)HID * H * VDIM];

// ---------------- ptx helpers ----------------
#define MMA_BF16(C, A, B0, B1)                                              \
    asm volatile(                                                           \
        "mma.sync.aligned.m16n8k16.row.col.f32.bf16.bf16.f32 "              \
        "{%0,%1,%2,%3},{%4,%5,%6,%7},{%8,%9},{%0,%1,%2,%3};\n"              \
        : "+f"(C[0]), "+f"(C[1]), "+f"(C[2]), "+f"(C[3])                    \
        : "r"(A[0]), "r"(A[1]), "r"(A[2]), "r"(A[3]), "r"(B0), "r"(B1));

#define MMA_F16(C, A, B0, B1)                                               \
    asm volatile(                                                           \
        "mma.sync.aligned.m16n8k16.row.col.f32.f16.f16.f32 "                \
        "{%0,%1,%2,%3},{%4,%5,%6,%7},{%8,%9},{%0,%1,%2,%3};\n"              \
        : "+f"(C[0]), "+f"(C[1]), "+f"(C[2]), "+f"(C[3])                    \
        : "r"(A[0]), "r"(A[1]), "r"(A[2]), "r"(A[3]), "r"(B0), "r"(B1));

#define LDSM_X4(R0, R1, R2, R3, ADDR)                                       \
    asm volatile("ldmatrix.sync.aligned.m8n8.x4.shared.b16 {%0,%1,%2,%3}, [%4];" \
        : "=r"(R0), "=r"(R1), "=r"(R2), "=r"(R3) : "r"(ADDR));

#define CP16(SM, G) asm volatile("cp.async.cg.shared.global [%0], [%1], 16;\n" :: "r"(SM), "l"(G))
#define CP_COMMIT   asm volatile("cp.async.commit_group;\n")
#define CP_WAIT0    asm volatile("cp.async.wait_group 0;\n")
#define CP_WAIT1    asm volatile("cp.async.wait_group 1;\n")

__device__ __forceinline__ void wr_pair(bf16* hi, bf16* lo, long long idx, float v) {
    bf16 h = __float2bfloat16(v);
    hi[idx] = h;
    lo[idx] = __float2bfloat16(v - __bfloat162float(h));
}
__device__ __forceinline__ void wr_pair16(__half* hi, __half* lo, long long idx, float v) {
    __half h = __float2half(v);
    hi[idx] = h;
    lo[idx] = __float2half(v - __half2float(h));
}

#define KT       32
#define PART     8192
#define BUF_SZ   32768          // bf16x3: 4 parts
#define SM_BF    98304          // 3 stages
#define BUF_F16  24576          // f16x2: 3 parts
#define SM_F16   73728          // 3 stages

// ---------------- bf16x3 tensor-core GEMM (2 CTAs/SM, 3-stage) ----------------
// pfp16: pair outputs written as fp16 (Chi/Clo cast) instead of bf16.
__global__ __launch_bounds__(256, 2)
void gemm_cp(const bf16* __restrict__ Ahi, const bf16* __restrict__ Alo,
             const bf16* __restrict__ Bhi, const bf16* __restrict__ Blo,
             float* __restrict__ Cfp, bf16* __restrict__ Chi, bf16* __restrict__ Clo,
             int K, int sa, int sb, int sc,
             long long aBS, long long bBS, long long cBS,
             float alpha, int mode, int pfp16)
{
    extern __shared__ char sm[];

    const int m0 = blockIdx.y * 128;
    const int n0 = blockIdx.x * 128;
    if ((mode & 1) && n0 > m0) return;
    int Keff = K;
    if (mode & 2) { int kl = m0 + 128; if (kl < Keff) Keff = kl; }

    Ahi += (long long)blockIdx.z * aBS + (long long)m0 * sa;
    Alo += (long long)blockIdx.z * aBS + (long long)m0 * sa;
    Bhi += (long long)blockIdx.z * bBS + (long long)n0 * sb;
    Blo += (long long)blockIdx.z * bBS + (long long)n0 * sb;
    const long long cOff = (long long)blockIdx.z * cBS + (long long)m0 * sc + n0;

    const int tid  = threadIdx.x;
    const int lane = tid & 31;
    const int wid  = tid >> 5;
    const int warpM = (wid & 3) * 32;
    const int warpN = (wid >> 2) * 64;
    const int srow  = tid >> 1;
    const int sch0  = (tid & 1) * 2;

    const uint32_t smBase = (uint32_t)__cvta_generic_to_shared(sm);

    float acc[2][8][4];
#pragma unroll
    for (int mi = 0; mi < 2; mi++)
#pragma unroll
        for (int ni = 0; ni < 8; ni++)
#pragma unroll
            for (int j = 0; j < 4; j++) acc[mi][ni][j] = 0.0f;

    auto issueTile = [&](int t) {
        const int kt = t * KT;
        const uint32_t sb0 = smBase + (t % 3) * BUF_SZ;
        const bf16* srcs[4] = {
            Ahi + (long long)srow * sa + kt,
            Alo + (long long)srow * sa + kt,
            Bhi + (long long)srow * sb + kt,
            Blo + (long long)srow * sb + kt };
        const int sw = (srow >> 1) & 3;
#pragma unroll
        for (int p = 0; p < 4; p++) {
            const uint32_t pb = sb0 + p * PART + srow * 64;
#pragma unroll
            for (int i = 0; i < 2; i++) {
                int ch = sch0 + i;
                CP16(pb + ((ch ^ sw) << 4), srcs[p] + ch * 8);
            }
        }
    };

    const int nT = Keff / KT;
    issueTile(0); CP_COMMIT;
    issueTile(1); CP_COMMIT;

    for (int t = 0; t < nT; t++) {
        if (t + 1 < nT) { CP_WAIT1; } else { CP_WAIT0; }
        __syncthreads();

        if (t + 2 < nT) { issueTile(t + 2); CP_COMMIT; }

        const uint32_t aHi = smBase + (t % 3) * BUF_SZ;
        const uint32_t aLo = aHi + PART;
        const uint32_t bHi = aLo + PART;
        const uint32_t bLo = bHi + PART;

#pragma unroll
        for (int ks = 0; ks < 2; ks++) {
            uint32_t ah[2][4], al[2][4];
            {
                const int lr = lane & 15;
                const int lc = lane >> 4;
#pragma unroll
                for (int mi = 0; mi < 2; mi++) {
                    int r  = warpM + mi * 16 + lr;
                    int ch = 2 * ks + lc;
                    uint32_t off = r * 64 + ((ch ^ ((r >> 1) & 3)) << 4);
                    LDSM_X4(ah[mi][0], ah[mi][1], ah[mi][2], ah[mi][3], aHi + off);
                    LDSM_X4(al[mi][0], al[mi][1], al[mi][2], al[mi][3], aLo + off);
                }
            }
            const int bn = (lane & 7) + ((lane >> 4) << 3);
            const int bc = 2 * ks + ((lane >> 3) & 1);
#pragma unroll
            for (int p = 0; p < 4; p++) {
                int r = warpN + p * 16 + bn;
                uint32_t off = r * 64 + ((bc ^ ((r >> 1) & 3)) << 4);
                uint32_t bh0, bh1, bh2, bh3, bl0, bl1, bl2, bl3;
                LDSM_X4(bh0, bh1, bh2, bh3, bHi + off);
                LDSM_X4(bl0, bl1, bl2, bl3, bLo + off);
#pragma unroll
                for (int mi = 0; mi < 2; mi++) {
                    MMA_BF16(acc[mi][2*p],   ah[mi], bh0, bh1);
                    MMA_BF16(acc[mi][2*p],   ah[mi], bl0, bl1);
                    MMA_BF16(acc[mi][2*p],   al[mi], bh0, bh1);
                    MMA_BF16(acc[mi][2*p+1], ah[mi], bh2, bh3);
                    MMA_BF16(acc[mi][2*p+1], ah[mi], bl2, bl3);
                    MMA_BF16(acc[mi][2*p+1], al[mi], bh2, bh3);
                }
            }
        }
    }

    // ---- epilogue ----
    const int g   = lane >> 2;
    const int tig = lane & 3;
#pragma unroll
    for (int mi = 0; mi < 2; mi++)
#pragma unroll
        for (int ni = 0; ni < 8; ni++) {
            int r  = warpM + mi * 16 + g;
            int cc = warpN + ni * 8 + 2 * tig;
            float v[4] = { alpha * acc[mi][ni][0], alpha * acc[mi][ni][1],
                           alpha * acc[mi][ni][2], alpha * acc[mi][ni][3] };
            long long i0 = cOff + (long long)r * sc + cc;
            long long i1 = cOff + (long long)(r + 8) * sc + cc;
            if (Cfp) {
                *(float2*)&Cfp[i0] = make_float2(v[0], v[1]);
                *(float2*)&Cfp[i1] = make_float2(v[2], v[3]);
            }
            if (Chi) {
                if (pfp16) {
                    __half* H16 = (__half*)Chi;
                    __half* L16 = (__half*)Clo;
                    wr_pair16(H16, L16, i0, v[0]); wr_pair16(H16, L16, i0 + 1, v[1]);
                    wr_pair16(H16, L16, i1, v[2]); wr_pair16(H16, L16, i1 + 1, v[3]);
                } else {
                    wr_pair(Chi, Clo, i0, v[0]); wr_pair(Chi, Clo, i0 + 1, v[1]);
                    wr_pair(Chi, Clo, i1, v[2]); wr_pair(Chi, Clo, i1 + 1, v[3]);
                }
            }
        }
}

// ---------------- f16x2 tensor-core GEMM (A = fp16 pair, B = fp16 hi only) ----------------
__global__ __launch_bounds__(256, 2)
void gemm_f16(const __half* __restrict__ Ahi, const __half* __restrict__ Alo,
              const __half* __restrict__ Bhi,
              float* __restrict__ Cfp, bf16* __restrict__ Chi, bf16* __restrict__ Clo,
              int K, int sa, int sb, int sc,
              long long aBS, long long bBS, long long cBS,
              float alpha, int mode)
{
    extern __shared__ char sm[];

    const int m0 = blockIdx.y * 128;
    const int n0 = blockIdx.x * 128;
    if ((mode & 1) && n0 > m0) return;
    int Keff = K;
    if (mode & 2) { int kl = m0 + 128; if (kl < Keff) Keff = kl; }

    Ahi += (long long)blockIdx.z * aBS + (long long)m0 * sa;
    Alo += (long long)blockIdx.z * aBS + (long long)m0 * sa;
    Bhi += (long long)blockIdx.z * bBS + (long long)n0 * sb;
    const long long cOff = (long long)blockIdx.z * cBS + (long long)m0 * sc + n0;

    const int tid  = threadIdx.x;
    const int lane = tid & 31;
    const int wid  = tid >> 5;
    const int warpM = (wid & 3) * 32;
    const int warpN = (wid >> 2) * 64;
    const int srow  = tid >> 1;
    const int sch0  = (tid & 1) * 2;

    const uint32_t smBase = (uint32_t)__cvta_generic_to_shared(sm);

    float acc[2][8][4];
#pragma unroll
    for (int mi = 0; mi < 2; mi++)
#pragma unroll
        for (int ni = 0; ni < 8; ni++)
#pragma unroll
            for (int j = 0; j < 4; j++) acc[mi][ni][j] = 0.0f;

    auto issueTile = [&](int t) {
        const int kt = t * KT;
        const uint32_t sb0 = smBase + (t % 3) * BUF_F16;
        const __half* srcs[3] = {
            Ahi + (long long)srow * sa + kt,
            Alo + (long long)srow * sa + kt,
            Bhi + (long long)srow * sb + kt };
        const int sw = (srow >> 1) & 3;
#pragma unroll
        for (int p = 0; p < 3; p++) {
            const uint32_t pb = sb0 + p * PART + srow * 64;
#pragma unroll
            for (int i = 0; i < 2; i++) {
                int ch = sch0 + i;
                CP16(pb + ((ch ^ sw) << 4), srcs[p] + ch * 8);
            }
        }
    };

    const int nT = Keff / KT;
    issueTile(0); CP_COMMIT;
    issueTile(1); CP_COMMIT;

    for (int t = 0; t < nT; t++) {
        if (t + 1 < nT) { CP_WAIT1; } else { CP_WAIT0; }
        __syncthreads();

        if (t + 2 < nT) { issueTile(t + 2); CP_COMMIT; }

        const uint32_t aHi = smBase + (t % 3) * BUF_F16;
        const uint32_t aLo = aHi + PART;
        const uint32_t bHi = aLo + PART;

#pragma unroll
        for (int ks = 0; ks < 2; ks++) {
            uint32_t ah[2][4], al[2][4];
            {
                const int lr = lane & 15;
                const int lc = lane >> 4;
#pragma unroll
                for (int mi = 0; mi < 2; mi++) {
                    int r  = warpM + mi * 16 + lr;
                    int ch = 2 * ks + lc;
                    uint32_t off = r * 64 + ((ch ^ ((r >> 1) & 3)) << 4);
                    LDSM_X4(ah[mi][0], ah[mi][1], ah[mi][2], ah[mi][3], aHi + off);
                    LDSM_X4(al[mi][0], al[mi][1], al[mi][2], al[mi][3], aLo + off);
                }
            }
            const int bn = (lane & 7) + ((lane >> 4) << 3);
            const int bc = 2 * ks + ((lane >> 3) & 1);
#pragma unroll
            for (int p = 0; p < 4; p++) {
                int r = warpN + p * 16 + bn;
                uint32_t off = r * 64 + ((bc ^ ((r >> 1) & 3)) << 4);
                uint32_t bh0, bh1, bh2, bh3;
                LDSM_X4(bh0, bh1, bh2, bh3, bHi + off);
#pragma unroll
                for (int mi = 0; mi < 2; mi++) {
                    MMA_F16(acc[mi][2*p],   ah[mi], bh0, bh1);
                    MMA_F16(acc[mi][2*p],   al[mi], bh0, bh1);
                    MMA_F16(acc[mi][2*p+1], ah[mi], bh2, bh3);
                    MMA_F16(acc[mi][2*p+1], al[mi], bh2, bh3);
                }
            }
        }
    }

    // ---- epilogue ----
    const int g   = lane >> 2;
    const int tig = lane & 3;
#pragma unroll
    for (int mi = 0; mi < 2; mi++)
#pragma unroll
        for (int ni = 0; ni < 8; ni++) {
            int r  = warpM + mi * 16 + g;
            int cc = warpN + ni * 8 + 2 * tig;
            float v[4] = { alpha * acc[mi][ni][0], alpha * acc[mi][ni][1],
                           alpha * acc[mi][ni][2], alpha * acc[mi][ni][3] };
            long long i0 = cOff + (long long)r * sc + cc;
            long long i1 = cOff + (long long)(r + 8) * sc + cc;
            if (Cfp) {
                *(float2*)&Cfp[i0] = make_float2(v[0], v[1]);
                *(float2*)&Cfp[i1] = make_float2(v[2], v[3]);
            }
            if (Chi) {
                wr_pair(Chi, Clo, i0, v[0]); wr_pair(Chi, Clo, i0 + 1, v[1]);
                wr_pair(Chi, Clo, i1, v[2]); wr_pair(Chi, Clo, i1 + 1, v[3]);
            }
        }
}

// ---------------- conversion kernels ----------------
__global__ void cvt_pair(const float4* __restrict__ src,
                         __nv_bfloat162* __restrict__ hi, __nv_bfloat162* __restrict__ lo,
                         int n4)
{
    int i = blockIdx.x * 256 + threadIdx.x;
    if (i >= n4) return;
    float4 v = src[i];
    bf16 hx = __float2bfloat16(v.x), hy = __float2bfloat16(v.y);
    bf16 hz = __float2bfloat16(v.z), hw = __float2bfloat16(v.w);
    __nv_bfloat162 h0; h0.x = hx; h0.y = hy;
    __nv_bfloat162 h1; h1.x = hz; h1.y = hw;
    hi[2*i] = h0; hi[2*i+1] = h1;
    __nv_bfloat162 l0, l1;
    l0.x = __float2bfloat16(v.x - __bfloat162float(hx));
    l0.y = __float2bfloat16(v.y - __bfloat162float(hy));
    l1.x = __float2bfloat16(v.z - __bfloat162float(hz));
    l1.y = __float2bfloat16(v.w - __bfloat162float(hw));
    lo[2*i] = l0; lo[2*i+1] = l1;
}

__global__ void cvt_f16hi(const float4* __restrict__ src, __half2* __restrict__ hi, int n4)
{
    int i = blockIdx.x * 256 + threadIdx.x;
    if (i >= n4) return;
    float4 v = src[i];
    hi[2*i]   = __floats2half2_rn(v.x, v.y);
    hi[2*i+1] = __floats2half2_rn(v.z, v.w);
}

// dst[q][p] = src[p][q], fp16 hi only
__global__ void tr_cvt_f16(const float* __restrict__ src, __half* __restrict__ hi,
                           int P, int Q)
{
    __shared__ float t[32][33];
    const int p0 = blockIdx.y * 32, q0 = blockIdx.x * 32;
    t[threadIdx.y][threadIdx.x] = src[(long long)(p0 + threadIdx.y) * Q + q0 + threadIdx.x];
    __syncthreads();
    hi[(long long)(q0 + threadIdx.y) * P + p0 + threadIdx.x] =
        __float2half(t[threadIdx.x][threadIdx.y]);
}

// ---------------- RoPE + pack ----------------
__global__ void rope_pack(const float* __restrict__ qf, const float* __restrict__ k_c,
                          const float* __restrict__ k_pe, const int* __restrict__ pos,
                          const float* __restrict__ cosc, const float* __restrict__ sinc)
{
    int t = blockIdx.x;
    int p = pos[t];
    const float* cs = cosc + (long long)p * (ROPE / 2);
    const float* sn = sinc + (long long)p * (ROPE / 2);

    for (int i = threadIdx.x; i < RANK; i += blockDim.x)
        wr_pair(g_kc_h, g_kc_l, (long long)t * DQK + i, k_c[(long long)t * RANK + i]);

    for (int j = threadIdx.x; j < ROPE / 2; j += blockDim.x) {
        float x1 = k_pe[(long long)t * ROPE + j];
        float x2 = k_pe[(long long)t * ROPE + j + ROPE / 2];
        float c = cs[j], s = sn[j];
        float r1 = x1 * c - x2 * s;
        float r2 = x2 * c + x1 * s;
        bf16 h1 = __float2bfloat16(r1), l1 = __float2bfloat16(r1 - __bfloat162float(h1));
        bf16 h2 = __float2bfloat16(r2), l2 = __float2bfloat16(r2 - __bfloat162float(h2));
#pragma unroll
        for (int h = 0; h < H; h++) {
            long long base = ((long long)h * TT + t) * DS + NOPE;
            g_kc2_h[base + j] = h1; g_kc2_l[base + j] = l1;
            g_kc2_h[base + ROPE / 2 + j] = h2; g_kc2_l[base + ROPE / 2 + j] = l2;
        }
    }

    for (int idx = threadIdx.x; idx < H * (ROPE / 2); idx += blockDim.x) {
        int h = idx / (ROPE / 2);
        int j = idx % (ROPE / 2);
        long long qb = (long long)t * QFW + h * DS + NOPE;
        float x1 = qf[qb + j];
        float x2 = qf[qb + ROPE / 2 + j];
        float c = cs[j], s = sn[j];
        wr_pair(g_qf_h, g_qf_l, qb + j,            x1 * c - x2 * s);
        wr_pair(g_qf_h, g_qf_l, qb + ROPE / 2 + j, x2 * c + x1 * s);
    }
}

// ---------------- causal softmax: fp16 pairs in (scaled), fp16 pairs out in-place ----------------
__global__ __launch_bounds__(256)
void softmax_causal(__half* __restrict__ Sh, __half* __restrict__ Sl,
                    const int* __restrict__ pos, float scale)
{
    const int t = blockIdx.x;
    const int h = blockIdx.y;
    const long long rb = ((long long)h * TT + t) * TT;
    const int pq = pos[t];
    const int limit = ((t >> 7) + 1) << 7;

    __shared__ float red[256];
    const int tid = threadIdx.x;

    float v[8];
    float m = -1e30f;
#pragma unroll
    for (int i = 0; i < 8; i++) {
        int s = tid + i * 256;
        v[i] = -1e30f;
        if (s < limit && pos[s] <= pq)
            v[i] = (__half2float(Sh[rb + s]) + __half2float(Sl[rb + s])) * scale;
        m = fmaxf(m, v[i]);
    }
    red[tid] = m; __syncthreads();
    for (int w = 128; w > 0; w >>= 1) {
        if (tid < w) red[tid] = fmaxf(red[tid], red[tid + w]);
        __syncthreads();
    }
    m = red[0];
    __syncthreads();

    float sum = 0.0f;
#pragma unroll
    for (int i = 0; i < 8; i++) {
        v[i] = __expf(v[i] - m);
        sum += v[i];
    }
    red[tid] = sum; __syncthreads();
    for (int w = 128; w > 0; w >>= 1) {
        if (tid < w) red[tid] += red[tid + w];
        __syncthreads();
    }
    float inv = 1.0f / red[0];

#pragma unroll
    for (int i = 0; i < 8; i++) {
        int s = tid + i * 256;
        if (s < limit) wr_pair16(Sh, Sl, rb + s, v[i] * inv);
    }
}

// ---------------- launch ----------------
extern "C" void kernel_launch(void* const* d_in, const int* in_sizes, int n_in,
                              void* d_out, int out_size)
{
    const float* q     = (const float*)d_in[0];
    const float* k_c   = (const float*)d_in[1];
    const float* k_pe  = (const float*)d_in[2];
    const int*   pos   = (const int*)  d_in[3];
    const float* wq    = (const float*)d_in[4];
    const float* kv_b  = (const float*)d_in[5];
    const float* wo    = (const float*)d_in[6];
    const float* cosc  = (const float*)d_in[7];
    const float* sinc  = (const float*)d_in[8];
    float* out = (float*)d_out;

    float *qf;
    cudaGetSymbolAddress((void**)&qf, g_qf);
    bf16 *q_h,*q_l,*wq_h,*wq_l,*qf_h,*qf_l,*kc_h,*kc_l,*kc2_h,*kc2_l,*kvb_h,*kvb_l,*ol_h,*ol_l;
    __half *Sp_h,*Sp_l,*kT16,*o_h,*o_l,*wo16;
    cudaGetSymbolAddress((void**)&q_h,  g_q_h);  cudaGetSymbolAddress((void**)&q_l,  g_q_l);
    cudaGetSymbolAddress((void**)&wq_h, g_wq_h); cudaGetSymbolAddress((void**)&wq_l, g_wq_l);
    cudaGetSymbolAddress((void**)&qf_h, g_qf_h); cudaGetSymbolAddress((void**)&qf_l, g_qf_l);
    cudaGetSymbolAddress((void**)&kc_h, g_kc_h); cudaGetSymbolAddress((void**)&kc_l, g_kc_l);
    cudaGetSymbolAddress((void**)&kc2_h,g_kc2_h);cudaGetSymbolAddress((void**)&kc2_l,g_kc2_l);
    cudaGetSymbolAddress((void**)&kvb_h,g_kvb_h);cudaGetSymbolAddress((void**)&kvb_l,g_kvb_l);
    cudaGetSymbolAddress((void**)&ol_h, g_ol_h); cudaGetSymbolAddress((void**)&ol_l, g_ol_l);
    cudaGetSymbolAddress((void**)&Sp_h, g_Sp_h); cudaGetSymbolAddress((void**)&Sp_l, g_Sp_l);
    cudaGetSymbolAddress((void**)&kT16, g_kT16);
    cudaGetSymbolAddress((void**)&o_h,  g_o_h);  cudaGetSymbolAddress((void**)&o_l,  g_o_l);
    cudaGetSymbolAddress((void**)&wo16, g_wo16);

    cudaFuncSetAttribute(gemm_cp,  cudaFuncAttributeMaxDynamicSharedMemorySize, SM_BF);
    cudaFuncSetAttribute(gemm_f16, cudaFuncAttributeMaxDynamicSharedMemorySize, SM_F16);

    const float scale = rsqrtf((float)(NOPE + ROPE));

    // ---- operand preconversion ----
    {
        int n4;
        n4 = TT * QIN / 4;
        cvt_pair<<<(n4 + 255) / 256, 256>>>((const float4*)q,  (__nv_bfloat162*)q_h,  (__nv_bfloat162*)q_l,  n4);
        n4 = QFW * QIN / 4;
        cvt_pair<<<(n4 + 255) / 256, 256>>>((const float4*)wq, (__nv_bfloat162*)wq_h, (__nv_bfloat162*)wq_l, n4);
        n4 = H * 256 * RANK / 4;
        cvt_pair<<<(n4 + 255) / 256, 256>>>((const float4*)kv_b, (__nv_bfloat162*)kvb_h, (__nv_bfloat162*)kvb_l, n4);
        n4 = HID * H * VDIM / 4;
        cvt_f16hi<<<(n4 + 255) / 256, 256>>>((const float4*)wo, (__half2*)wo16, n4);
        tr_cvt_f16<<<dim3(RANK / 32, TT / 32, 1), dim3(32, 32)>>>(k_c, kT16, TT, RANK);
    }

    // 1) qf = q @ wq^T  (fp32 qf + bf16 pairs in qc2 layout)
    gemm_cp<<<dim3(QFW / 128, TT / 128, 1), 256, SM_BF>>>(
        q_h, q_l, wq_h, wq_l, qf, qf_h, qf_l,
        QIN, QIN, QIN, QFW, 0, 0, 0, 1.0f, 0, 0);

    // 2) rope + pack
    rope_pack<<<TT, 256>>>(qf, k_c, k_pe, pos, cosc, sinc);

    // 3) k_up_h = k_c @ w_uk_h -> kc2[:,0:128] bf16 pairs
    gemm_cp<<<dim3(1, TT / 128, H), 256, SM_BF>>>(
        kc_h, kc_l, kvb_h, kvb_l, nullptr, kc2_h, kc2_l,
        RANK, DQK, RANK, DS,
        0, (long long)256 * RANK, (long long)TT * DS, 1.0f, 0, 0);

    // 4) S_h = Qc2_h @ Kc2_h^T : K=192, causal skip, fp16 pairs out
    gemm_cp<<<dim3(TT / 128, TT / 128, H), 256, SM_BF>>>(
        qf_h, qf_l, kc2_h, kc2_l, nullptr, (bf16*)Sp_h, (bf16*)Sp_l,
        DS, QFW, DS, TT,
        (long long)DS, (long long)TT * DS, (long long)TT * TT, 1.0f, 1, 1);

    // 5) softmax in-place on fp16 pairs (scale on load)
    softmax_causal<<<dim3(TT, H), 256>>>(Sp_h, Sp_l, pos, scale);

    // 6) olat_h = P_h @ k_c : f16x2, K limited to m0+128, bf16 pairs out
    gemm_f16<<<dim3(RANK / 128, TT / 128, H), 256, SM_F16>>>(
        Sp_h, Sp_l, kT16, nullptr, ol_h, ol_l,
        TT, TT, TT, H * RANK,
        (long long)TT * TT, 0, (long long)RANK, 1.0f, 2);

    // 7) o_h = olat_h @ w_uv_h : bf16x3, fp16 pairs out
    gemm_cp<<<dim3(VDIM / 128, TT / 128, H), 256, SM_BF>>>(
        ol_h, ol_l, kvb_h + (long long)NOPE * RANK, kvb_l + (long long)NOPE * RANK,
        nullptr, (bf16*)o_h, (bf16*)o_l,
        RANK, H * RANK, RANK, H * VDIM,
        (long long)RANK, (long long)256 * RANK, (long long)VDIM, 1.0f, 0, 1);

    // 8) out = o @ wo^T : f16x2, fp32 out
    gemm_f16<<<dim3(HID / 128, TT / 128, 1), 256, SM_F16>>>(
        o_h, o_l, wo16, out, nullptr, nullptr,
        H * VDIM, H * VDIM, H * VDIM, HID, 0, 0, 0, 1.0f, 0);
}

// round 14
// speedup vs baseline: 1.6089x; 1.1324x over previous
#include <cuda_runtime.h>
#include <cuda_bf16.h>
#include <cuda_fp16.h>
#include <stdint.h>
#include <math.h>

// ---------------- problem constants ----------------
#define TT    2048
#define H     16
#define NOPE  128
#define ROPE  64
#define VDIM  128
#define RANK  512
#define QIN   1536
#define HID   7168
#define DQK   576
#define DS    192
#define QFW   (H * (NOPE + ROPE))   // 3072

typedef __nv_bfloat16 bf16;

// fp32 intermediates
static __device__ float g_qf[(size_t)TT * QFW];

// bf16 hi/lo pairs (score path: bf16x3)
static __device__ bf16 g_q_h  [(size_t)TT * QIN],      g_q_l  [(size_t)TT * QIN];
static __device__ bf16 g_wq_h [(size_t)QFW * QIN],     g_wq_l [(size_t)QFW * QIN];
static __device__ bf16 g_qf_h [(size_t)TT * QFW],      g_qf_l [(size_t)TT * QFW];
static __device__ bf16 g_kc_h [(size_t)TT * DQK],      g_kc_l [(size_t)TT * DQK];
static __device__ bf16 g_kc2_h[(size_t)H * TT * DS],   g_kc2_l[(size_t)H * TT * DS];
static __device__ bf16 g_kvb_h[(size_t)H * 256 * RANK], g_kvb_l[(size_t)H * 256 * RANK];
static __device__ bf16 g_ol_h [(size_t)TT * H * RANK], g_ol_l [(size_t)TT * H * RANK];

// fp16 operands (value path)
static __device__ __half g_Sp_h[(size_t)H * TT * TT];      // scores -> probs, hi only
static __device__ __half g_kT16[(size_t)RANK * TT];
static __device__ __half g_o_h [(size_t)TT * H * VDIM], g_o_l [(size_t)TT * H * VDIM];
static __device__ __half g_wo16[(size_t)HID * H * VDIM];

// ---------------- ptx helpers ----------------
#define MMA_BF16(C, A, B0, B1)                                              \
    asm volatile(                                                           \
        "mma.sync.aligned.m16n8k16.row.col.f32.bf16.bf16.f32 "              \
        "{%0,%1,%2,%3},{%4,%5,%6,%7},{%8,%9},{%0,%1,%2,%3};\n"              \
        : "+f"(C[0]), "+f"(C[1]), "+f"(C[2]), "+f"(C[3])                    \
        : "r"(A[0]), "r"(A[1]), "r"(A[2]), "r"(A[3]), "r"(B0), "r"(B1));

#define MMA_F16(C, A, B0, B1)                                               \
    asm volatile(                                                           \
        "mma.sync.aligned.m16n8k16.row.col.f32.f16.f16.f32 "                \
        "{%0,%1,%2,%3},{%4,%5,%6,%7},{%8,%9},{%0,%1,%2,%3};\n"              \
        : "+f"(C[0]), "+f"(C[1]), "+f"(C[2]), "+f"(C[3])                    \
        : "r"(A[0]), "r"(A[1]), "r"(A[2]), "r"(A[3]), "r"(B0), "r"(B1));

#define LDSM_X4(R0, R1, R2, R3, ADDR)                                       \
    asm volatile("ldmatrix.sync.aligned.m8n8.x4.shared.b16 {%0,%1,%2,%3}, [%4];" \
        : "=r"(R0), "=r"(R1), "=r"(R2), "=r"(R3) : "r"(ADDR));

#define CP16(SM, G) asm volatile("cp.async.cg.shared.global [%0], [%1], 16;\n" :: "r"(SM), "l"(G))
#define CP_COMMIT   asm volatile("cp.async.commit_group;\n")
#define CP_WAIT0    asm volatile("cp.async.wait_group 0;\n")
#define CP_WAIT1    asm volatile("cp.async.wait_group 1;\n")

__device__ __forceinline__ void wr_pair(bf16* hi, bf16* lo, long long idx, float v) {
    bf16 h = __float2bfloat16(v);
    hi[idx] = h;
    lo[idx] = __float2bfloat16(v - __bfloat162float(h));
}
__device__ __forceinline__ void wr_pair16(__half* hi, __half* lo, long long idx, float v) {
    __half h = __float2half(v);
    hi[idx] = h;
    lo[idx] = __float2half(v - __half2float(h));
}

#define KT       32
#define PART     8192
#define BUF_SZ   32768          // bf16x3: 4 parts
#define SM_BF    98304          // 3 stages
#define SM_F16MAX 73728         // f16: up to 3 parts x 3 stages

// ---------------- bf16x3 tensor-core GEMM (2 CTAs/SM, 3-stage) ----------------
// pfp16: 0 = bf16 pairs out; 1 = fp16 pairs out; 2 = fp16 HI ONLY out.
__global__ __launch_bounds__(256, 2)
void gemm_cp(const bf16* __restrict__ Ahi, const bf16* __restrict__ Alo,
             const bf16* __restrict__ Bhi, const bf16* __restrict__ Blo,
             float* __restrict__ Cfp, bf16* __restrict__ Chi, bf16* __restrict__ Clo,
             int K, int sa, int sb, int sc,
             long long aBS, long long bBS, long long cBS,
             float alpha, int mode, int pfp16)
{
    extern __shared__ char sm[];

    const int m0 = blockIdx.y * 128;
    const int n0 = blockIdx.x * 128;
    if ((mode & 1) && n0 > m0) return;
    int Keff = K;
    if (mode & 2) { int kl = m0 + 128; if (kl < Keff) Keff = kl; }

    Ahi += (long long)blockIdx.z * aBS + (long long)m0 * sa;
    Alo += (long long)blockIdx.z * aBS + (long long)m0 * sa;
    Bhi += (long long)blockIdx.z * bBS + (long long)n0 * sb;
    Blo += (long long)blockIdx.z * bBS + (long long)n0 * sb;
    const long long cOff = (long long)blockIdx.z * cBS + (long long)m0 * sc + n0;

    const int tid  = threadIdx.x;
    const int lane = tid & 31;
    const int wid  = tid >> 5;
    const int warpM = (wid & 3) * 32;
    const int warpN = (wid >> 2) * 64;
    const int srow  = tid >> 1;
    const int sch0  = (tid & 1) * 2;

    const uint32_t smBase = (uint32_t)__cvta_generic_to_shared(sm);

    float acc[2][8][4];
#pragma unroll
    for (int mi = 0; mi < 2; mi++)
#pragma unroll
        for (int ni = 0; ni < 8; ni++)
#pragma unroll
            for (int j = 0; j < 4; j++) acc[mi][ni][j] = 0.0f;

    auto issueTile = [&](int t) {
        const int kt = t * KT;
        const uint32_t sb0 = smBase + (t % 3) * BUF_SZ;
        const bf16* srcs[4] = {
            Ahi + (long long)srow * sa + kt,
            Alo + (long long)srow * sa + kt,
            Bhi + (long long)srow * sb + kt,
            Blo + (long long)srow * sb + kt };
        const int sw = (srow >> 1) & 3;
#pragma unroll
        for (int p = 0; p < 4; p++) {
            const uint32_t pb = sb0 + p * PART + srow * 64;
#pragma unroll
            for (int i = 0; i < 2; i++) {
                int ch = sch0 + i;
                CP16(pb + ((ch ^ sw) << 4), srcs[p] + ch * 8);
            }
        }
    };

    const int nT = Keff / KT;
    issueTile(0); CP_COMMIT;
    issueTile(1); CP_COMMIT;

    for (int t = 0; t < nT; t++) {
        if (t + 1 < nT) { CP_WAIT1; } else { CP_WAIT0; }
        __syncthreads();

        if (t + 2 < nT) { issueTile(t + 2); CP_COMMIT; }

        const uint32_t aHi = smBase + (t % 3) * BUF_SZ;
        const uint32_t aLo = aHi + PART;
        const uint32_t bHi = aLo + PART;
        const uint32_t bLo = bHi + PART;

#pragma unroll
        for (int ks = 0; ks < 2; ks++) {
            uint32_t ah[2][4], al[2][4];
            {
                const int lr = lane & 15;
                const int lc = lane >> 4;
#pragma unroll
                for (int mi = 0; mi < 2; mi++) {
                    int r  = warpM + mi * 16 + lr;
                    int ch = 2 * ks + lc;
                    uint32_t off = r * 64 + ((ch ^ ((r >> 1) & 3)) << 4);
                    LDSM_X4(ah[mi][0], ah[mi][1], ah[mi][2], ah[mi][3], aHi + off);
                    LDSM_X4(al[mi][0], al[mi][1], al[mi][2], al[mi][3], aLo + off);
                }
            }
            const int bn = (lane & 7) + ((lane >> 4) << 3);
            const int bc = 2 * ks + ((lane >> 3) & 1);
#pragma unroll
            for (int p = 0; p < 4; p++) {
                int r = warpN + p * 16 + bn;
                uint32_t off = r * 64 + ((bc ^ ((r >> 1) & 3)) << 4);
                uint32_t bh0, bh1, bh2, bh3, bl0, bl1, bl2, bl3;
                LDSM_X4(bh0, bh1, bh2, bh3, bHi + off);
                LDSM_X4(bl0, bl1, bl2, bl3, bLo + off);
#pragma unroll
                for (int mi = 0; mi < 2; mi++) {
                    MMA_BF16(acc[mi][2*p],   ah[mi], bh0, bh1);
                    MMA_BF16(acc[mi][2*p],   ah[mi], bl0, bl1);
                    MMA_BF16(acc[mi][2*p],   al[mi], bh0, bh1);
                    MMA_BF16(acc[mi][2*p+1], ah[mi], bh2, bh3);
                    MMA_BF16(acc[mi][2*p+1], ah[mi], bl2, bl3);
                    MMA_BF16(acc[mi][2*p+1], al[mi], bh2, bh3);
                }
            }
        }
    }

    // ---- epilogue ----
    const int g   = lane >> 2;
    const int tig = lane & 3;
#pragma unroll
    for (int mi = 0; mi < 2; mi++)
#pragma unroll
        for (int ni = 0; ni < 8; ni++) {
            int r  = warpM + mi * 16 + g;
            int cc = warpN + ni * 8 + 2 * tig;
            float v[4] = { alpha * acc[mi][ni][0], alpha * acc[mi][ni][1],
                           alpha * acc[mi][ni][2], alpha * acc[mi][ni][3] };
            long long i0 = cOff + (long long)r * sc + cc;
            long long i1 = cOff + (long long)(r + 8) * sc + cc;
            if (Cfp) {
                *(float2*)&Cfp[i0] = make_float2(v[0], v[1]);
                *(float2*)&Cfp[i1] = make_float2(v[2], v[3]);
            }
            if (Chi) {
                if (pfp16 == 2) {
                    __half* H16 = (__half*)Chi;
                    __half2 a2 = __floats2half2_rn(v[0], v[1]);
                    __half2 b2 = __floats2half2_rn(v[2], v[3]);
                    *(__half2*)&H16[i0] = a2;
                    *(__half2*)&H16[i1] = b2;
                } else if (pfp16 == 1) {
                    __half* H16 = (__half*)Chi;
                    __half* L16 = (__half*)Clo;
                    wr_pair16(H16, L16, i0, v[0]); wr_pair16(H16, L16, i0 + 1, v[1]);
                    wr_pair16(H16, L16, i1, v[2]); wr_pair16(H16, L16, i1 + 1, v[3]);
                } else {
                    wr_pair(Chi, Clo, i0, v[0]); wr_pair(Chi, Clo, i0 + 1, v[1]);
                    wr_pair(Chi, Clo, i1, v[2]); wr_pair(Chi, Clo, i1 + 1, v[3]);
                }
            }
        }
}

// ---------------- f16 tensor-core GEMM, 1 or 2 A-terms ----------------
// two=1: A = (Ahi + Alo) pair, 2 MMAs/acc. two=0: A = Ahi only, 1 MMA/acc.
__global__ __launch_bounds__(256, 2)
void gemm_f16(const __half* __restrict__ Ahi, const __half* __restrict__ Alo,
              const __half* __restrict__ Bhi,
              float* __restrict__ Cfp, bf16* __restrict__ Chi, bf16* __restrict__ Clo,
              int K, int sa, int sb, int sc,
              long long aBS, long long bBS, long long cBS,
              float alpha, int mode, int two)
{
    extern __shared__ char sm[];

    const int m0 = blockIdx.y * 128;
    const int n0 = blockIdx.x * 128;
    if ((mode & 1) && n0 > m0) return;
    int Keff = K;
    if (mode & 2) { int kl = m0 + 128; if (kl < Keff) Keff = kl; }

    Ahi += (long long)blockIdx.z * aBS + (long long)m0 * sa;
    Alo += (long long)blockIdx.z * aBS + (long long)m0 * sa;
    Bhi += (long long)blockIdx.z * bBS + (long long)n0 * sb;
    const long long cOff = (long long)blockIdx.z * cBS + (long long)m0 * sc + n0;

    const int tid  = threadIdx.x;
    const int lane = tid & 31;
    const int wid  = tid >> 5;
    const int warpM = (wid & 3) * 32;
    const int warpN = (wid >> 2) * 64;
    const int srow  = tid >> 1;
    const int sch0  = (tid & 1) * 2;

    const int nparts = two ? 3 : 2;
    const uint32_t BUF = nparts * PART;
    const uint32_t smBase = (uint32_t)__cvta_generic_to_shared(sm);

    float acc[2][8][4];
#pragma unroll
    for (int mi = 0; mi < 2; mi++)
#pragma unroll
        for (int ni = 0; ni < 8; ni++)
#pragma unroll
            for (int j = 0; j < 4; j++) acc[mi][ni][j] = 0.0f;

    auto issueTile = [&](int t) {
        const int kt = t * KT;
        const uint32_t sb0 = smBase + (t % 3) * BUF;
        const int sw = (srow >> 1) & 3;
        // part 0: Ahi
        {
            const __half* g = Ahi + (long long)srow * sa + kt;
            const uint32_t pb = sb0 + srow * 64;
#pragma unroll
            for (int i = 0; i < 2; i++) {
                int ch = sch0 + i;
                CP16(pb + ((ch ^ sw) << 4), g + ch * 8);
            }
        }
        // part 1: Alo (only if two)
        if (two) {
            const __half* g = Alo + (long long)srow * sa + kt;
            const uint32_t pb = sb0 + PART + srow * 64;
#pragma unroll
            for (int i = 0; i < 2; i++) {
                int ch = sch0 + i;
                CP16(pb + ((ch ^ sw) << 4), g + ch * 8);
            }
        }
        // last part: Bhi
        {
            const __half* g = Bhi + (long long)srow * sb + kt;
            const uint32_t pb = sb0 + (nparts - 1) * PART + srow * 64;
#pragma unroll
            for (int i = 0; i < 2; i++) {
                int ch = sch0 + i;
                CP16(pb + ((ch ^ sw) << 4), g + ch * 8);
            }
        }
    };

    const int nT = Keff / KT;
    issueTile(0); CP_COMMIT;
    issueTile(1); CP_COMMIT;

    for (int t = 0; t < nT; t++) {
        if (t + 1 < nT) { CP_WAIT1; } else { CP_WAIT0; }
        __syncthreads();

        if (t + 2 < nT) { issueTile(t + 2); CP_COMMIT; }

        const uint32_t aHi = smBase + (t % 3) * BUF;
        const uint32_t aLo = aHi + PART;
        const uint32_t bHi = aHi + (nparts - 1) * PART;

#pragma unroll
        for (int ks = 0; ks < 2; ks++) {
            uint32_t ah[2][4], al[2][4];
            {
                const int lr = lane & 15;
                const int lc = lane >> 4;
#pragma unroll
                for (int mi = 0; mi < 2; mi++) {
                    int r  = warpM + mi * 16 + lr;
                    int ch = 2 * ks + lc;
                    uint32_t off = r * 64 + ((ch ^ ((r >> 1) & 3)) << 4);
                    LDSM_X4(ah[mi][0], ah[mi][1], ah[mi][2], ah[mi][3], aHi + off);
                    if (two) LDSM_X4(al[mi][0], al[mi][1], al[mi][2], al[mi][3], aLo + off);
                }
            }
            const int bn = (lane & 7) + ((lane >> 4) << 3);
            const int bc = 2 * ks + ((lane >> 3) & 1);
#pragma unroll
            for (int p = 0; p < 4; p++) {
                int r = warpN + p * 16 + bn;
                uint32_t off = r * 64 + ((bc ^ ((r >> 1) & 3)) << 4);
                uint32_t bh0, bh1, bh2, bh3;
                LDSM_X4(bh0, bh1, bh2, bh3, bHi + off);
#pragma unroll
                for (int mi = 0; mi < 2; mi++) {
                    MMA_F16(acc[mi][2*p],   ah[mi], bh0, bh1);
                    MMA_F16(acc[mi][2*p+1], ah[mi], bh2, bh3);
                    if (two) {
                        MMA_F16(acc[mi][2*p],   al[mi], bh0, bh1);
                        MMA_F16(acc[mi][2*p+1], al[mi], bh2, bh3);
                    }
                }
            }
        }
    }

    // ---- epilogue ----
    const int g   = lane >> 2;
    const int tig = lane & 3;
#pragma unroll
    for (int mi = 0; mi < 2; mi++)
#pragma unroll
        for (int ni = 0; ni < 8; ni++) {
            int r  = warpM + mi * 16 + g;
            int cc = warpN + ni * 8 + 2 * tig;
            float v[4] = { alpha * acc[mi][ni][0], alpha * acc[mi][ni][1],
                           alpha * acc[mi][ni][2], alpha * acc[mi][ni][3] };
            long long i0 = cOff + (long long)r * sc + cc;
            long long i1 = cOff + (long long)(r + 8) * sc + cc;
            if (Cfp) {
                *(float2*)&Cfp[i0] = make_float2(v[0], v[1]);
                *(float2*)&Cfp[i1] = make_float2(v[2], v[3]);
            }
            if (Chi) {
                wr_pair(Chi, Clo, i0, v[0]); wr_pair(Chi, Clo, i0 + 1, v[1]);
                wr_pair(Chi, Clo, i1, v[2]); wr_pair(Chi, Clo, i1 + 1, v[3]);
            }
        }
}

// ---------------- conversion kernels ----------------
__global__ void cvt_pair(const float4* __restrict__ src,
                         __nv_bfloat162* __restrict__ hi, __nv_bfloat162* __restrict__ lo,
                         int n4)
{
    int i = blockIdx.x * 256 + threadIdx.x;
    if (i >= n4) return;
    float4 v = src[i];
    bf16 hx = __float2bfloat16(v.x), hy = __float2bfloat16(v.y);
    bf16 hz = __float2bfloat16(v.z), hw = __float2bfloat16(v.w);
    __nv_bfloat162 h0; h0.x = hx; h0.y = hy;
    __nv_bfloat162 h1; h1.x = hz; h1.y = hw;
    hi[2*i] = h0; hi[2*i+1] = h1;
    __nv_bfloat162 l0, l1;
    l0.x = __float2bfloat16(v.x - __bfloat162float(hx));
    l0.y = __float2bfloat16(v.y - __bfloat162float(hy));
    l1.x = __float2bfloat16(v.z - __bfloat162float(hz));
    l1.y = __float2bfloat16(v.w - __bfloat162float(hw));
    lo[2*i] = l0; lo[2*i+1] = l1;
}

__global__ void cvt_f16hi(const float4* __restrict__ src, __half2* __restrict__ hi, int n4)
{
    int i = blockIdx.x * 256 + threadIdx.x;
    if (i >= n4) return;
    float4 v = src[i];
    hi[2*i]   = __floats2half2_rn(v.x, v.y);
    hi[2*i+1] = __floats2half2_rn(v.z, v.w);
}

// dst[q][p] = src[p][q], fp16 hi only
__global__ void tr_cvt_f16(const float* __restrict__ src, __half* __restrict__ hi,
                           int P, int Q)
{
    __shared__ float t[32][33];
    const int p0 = blockIdx.y * 32, q0 = blockIdx.x * 32;
    t[threadIdx.y][threadIdx.x] = src[(long long)(p0 + threadIdx.y) * Q + q0 + threadIdx.x];
    __syncthreads();
    hi[(long long)(q0 + threadIdx.y) * P + p0 + threadIdx.x] =
        __float2half(t[threadIdx.x][threadIdx.y]);
}

// ---------------- RoPE + pack ----------------
__global__ void rope_pack(const float* __restrict__ qf, const float* __restrict__ k_c,
                          const float* __restrict__ k_pe, const int* __restrict__ pos,
                          const float* __restrict__ cosc, const float* __restrict__ sinc)
{
    int t = blockIdx.x;
    int p = pos[t];
    const float* cs = cosc + (long long)p * (ROPE / 2);
    const float* sn = sinc + (long long)p * (ROPE / 2);

    for (int i = threadIdx.x; i < RANK; i += blockDim.x)
        wr_pair(g_kc_h, g_kc_l, (long long)t * DQK + i, k_c[(long long)t * RANK + i]);

    for (int j = threadIdx.x; j < ROPE / 2; j += blockDim.x) {
        float x1 = k_pe[(long long)t * ROPE + j];
        float x2 = k_pe[(long long)t * ROPE + j + ROPE / 2];
        float c = cs[j], s = sn[j];
        float r1 = x1 * c - x2 * s;
        float r2 = x2 * c + x1 * s;
        bf16 h1 = __float2bfloat16(r1), l1 = __float2bfloat16(r1 - __bfloat162float(h1));
        bf16 h2 = __float2bfloat16(r2), l2 = __float2bfloat16(r2 - __bfloat162float(h2));
#pragma unroll
        for (int h = 0; h < H; h++) {
            long long base = ((long long)h * TT + t) * DS + NOPE;
            g_kc2_h[base + j] = h1; g_kc2_l[base + j] = l1;
            g_kc2_h[base + ROPE / 2 + j] = h2; g_kc2_l[base + ROPE / 2 + j] = l2;
        }
    }

    for (int idx = threadIdx.x; idx < H * (ROPE / 2); idx += blockDim.x) {
        int h = idx / (ROPE / 2);
        int j = idx % (ROPE / 2);
        long long qb = (long long)t * QFW + h * DS + NOPE;
        float x1 = qf[qb + j];
        float x2 = qf[qb + ROPE / 2 + j];
        float c = cs[j], s = sn[j];
        wr_pair(g_qf_h, g_qf_l, qb + j,            x1 * c - x2 * s);
        wr_pair(g_qf_h, g_qf_l, qb + ROPE / 2 + j, x2 * c + x1 * s);
    }
}

// ---------------- causal softmax: fp16 hi in (scaled), fp16 hi out in-place ----------------
__global__ __launch_bounds__(256)
void softmax_causal(__half* __restrict__ Sh, const int* __restrict__ pos, float scale)
{
    const int t = blockIdx.x;
    const int h = blockIdx.y;
    const long long rb = ((long long)h * TT + t) * TT;
    const int pq = pos[t];
    const int limit = ((t >> 7) + 1) << 7;

    __shared__ float red[256];
    const int tid = threadIdx.x;

    float v[8];
    float m = -1e30f;
#pragma unroll
    for (int i = 0; i < 8; i++) {
        int s = tid + i * 256;
        v[i] = -1e30f;
        if (s < limit && pos[s] <= pq) v[i] = __half2float(Sh[rb + s]) * scale;
        m = fmaxf(m, v[i]);
    }
    red[tid] = m; __syncthreads();
    for (int w = 128; w > 0; w >>= 1) {
        if (tid < w) red[tid] = fmaxf(red[tid], red[tid + w]);
        __syncthreads();
    }
    m = red[0];
    __syncthreads();

    float sum = 0.0f;
#pragma unroll
    for (int i = 0; i < 8; i++) {
        v[i] = __expf(v[i] - m);
        sum += v[i];
    }
    red[tid] = sum; __syncthreads();
    for (int w = 128; w > 0; w >>= 1) {
        if (tid < w) red[tid] += red[tid + w];
        __syncthreads();
    }
    float inv = 1.0f / red[0];

#pragma unroll
    for (int i = 0; i < 8; i++) {
        int s = tid + i * 256;
        if (s < limit) Sh[rb + s] = __float2half(v[i] * inv);
    }
}

// ---------------- launch ----------------
extern "C" void kernel_launch(void* const* d_in, const int* in_sizes, int n_in,
                              void* d_out, int out_size)
{
    const float* q     = (const float*)d_in[0];
    const float* k_c   = (const float*)d_in[1];
    const float* k_pe  = (const float*)d_in[2];
    const int*   pos   = (const int*)  d_in[3];
    const float* wq    = (const float*)d_in[4];
    const float* kv_b  = (const float*)d_in[5];
    const float* wo    = (const float*)d_in[6];
    const float* cosc  = (const float*)d_in[7];
    const float* sinc  = (const float*)d_in[8];
    float* out = (float*)d_out;

    float *qf;
    cudaGetSymbolAddress((void**)&qf, g_qf);
    bf16 *q_h,*q_l,*wq_h,*wq_l,*qf_h,*qf_l,*kc_h,*kc_l,*kc2_h,*kc2_l,*kvb_h,*kvb_l,*ol_h,*ol_l;
    __half *Sp_h,*kT16,*o_h,*o_l,*wo16;
    cudaGetSymbolAddress((void**)&q_h,  g_q_h);  cudaGetSymbolAddress((void**)&q_l,  g_q_l);
    cudaGetSymbolAddress((void**)&wq_h, g_wq_h); cudaGetSymbolAddress((void**)&wq_l, g_wq_l);
    cudaGetSymbolAddress((void**)&qf_h, g_qf_h); cudaGetSymbolAddress((void**)&qf_l, g_qf_l);
    cudaGetSymbolAddress((void**)&kc_h, g_kc_h); cudaGetSymbolAddress((void**)&kc_l, g_kc_l);
    cudaGetSymbolAddress((void**)&kc2_h,g_kc2_h);cudaGetSymbolAddress((void**)&kc2_l,g_kc2_l);
    cudaGetSymbolAddress((void**)&kvb_h,g_kvb_h);cudaGetSymbolAddress((void**)&kvb_l,g_kvb_l);
    cudaGetSymbolAddress((void**)&ol_h, g_ol_h); cudaGetSymbolAddress((void**)&ol_l, g_ol_l);
    cudaGetSymbolAddress((void**)&Sp_h, g_Sp_h);
    cudaGetSymbolAddress((void**)&kT16, g_kT16);
    cudaGetSymbolAddress((void**)&o_h,  g_o_h);  cudaGetSymbolAddress((void**)&o_l,  g_o_l);
    cudaGetSymbolAddress((void**)&wo16, g_wo16);

    cudaFuncSetAttribute(gemm_cp,  cudaFuncAttributeMaxDynamicSharedMemorySize, SM_BF);
    cudaFuncSetAttribute(gemm_f16, cudaFuncAttributeMaxDynamicSharedMemorySize, SM_F16MAX);

    const float scale = rsqrtf((float)(NOPE + ROPE));

    // ---- operand preconversion ----
    {
        int n4;
        n4 = TT * QIN / 4;
        cvt_pair<<<(n4 + 255) / 256, 256>>>((const float4*)q,  (__nv_bfloat162*)q_h,  (__nv_bfloat162*)q_l,  n4);
        n4 = QFW * QIN / 4;
        cvt_pair<<<(n4 + 255) / 256, 256>>>((const float4*)wq, (__nv_bfloat162*)wq_h, (__nv_bfloat162*)wq_l, n4);
        n4 = H * 256 * RANK / 4;
        cvt_pair<<<(n4 + 255) / 256, 256>>>((const float4*)kv_b, (__nv_bfloat162*)kvb_h, (__nv_bfloat162*)kvb_l, n4);
        n4 = HID * H * VDIM / 4;
        cvt_f16hi<<<(n4 + 255) / 256, 256>>>((const float4*)wo, (__half2*)wo16, n4);
        tr_cvt_f16<<<dim3(RANK / 32, TT / 32, 1), dim3(32, 32)>>>(k_c, kT16, TT, RANK);
    }

    // 1) qf = q @ wq^T  (fp32 qf + bf16 pairs in qc2 layout)
    gemm_cp<<<dim3(QFW / 128, TT / 128, 1), 256, SM_BF>>>(
        q_h, q_l, wq_h, wq_l, qf, qf_h, qf_l,
        QIN, QIN, QIN, QFW, 0, 0, 0, 1.0f, 0, 0);

    // 2) rope + pack
    rope_pack<<<TT, 256>>>(qf, k_c, k_pe, pos, cosc, sinc);

    // 3) k_up_h = k_c @ w_uk_h -> kc2[:,0:128] bf16 pairs
    gemm_cp<<<dim3(1, TT / 128, H), 256, SM_BF>>>(
        kc_h, kc_l, kvb_h, kvb_l, nullptr, kc2_h, kc2_l,
        RANK, DQK, RANK, DS,
        0, (long long)256 * RANK, (long long)TT * DS, 1.0f, 0, 0);

    // 4) S_h = Qc2_h @ Kc2_h^T : K=192, causal skip, fp16 HI ONLY out
    gemm_cp<<<dim3(TT / 128, TT / 128, H), 256, SM_BF>>>(
        qf_h, qf_l, kc2_h, kc2_l, nullptr, (bf16*)Sp_h, nullptr,
        DS, QFW, DS, TT,
        (long long)DS, (long long)TT * DS, (long long)TT * TT, 1.0f, 1, 2);

    // 5) softmax in-place on fp16 hi (scale on load)
    softmax_causal<<<dim3(TT, H), 256>>>(Sp_h, pos, scale);

    // 6) olat_h = P_h @ k_c : f16 1-term, K limited to m0+128, bf16 pairs out
    gemm_f16<<<dim3(RANK / 128, TT / 128, H), 256, 3 * 2 * PART>>>(
        Sp_h, Sp_h, kT16, nullptr, ol_h, ol_l,
        TT, TT, TT, H * RANK,
        (long long)TT * TT, 0, (long long)RANK, 1.0f, 2, 0);

    // 7) o_h = olat_h @ w_uv_h : bf16x3, fp16 pairs out
    gemm_cp<<<dim3(VDIM / 128, TT / 128, H), 256, SM_BF>>>(
        ol_h, ol_l, kvb_h + (long long)NOPE * RANK, kvb_l + (long long)NOPE * RANK,
        nullptr, (bf16*)o_h, (bf16*)o_l,
        RANK, H * RANK, RANK, H * VDIM,
        (long long)RANK, (long long)256 * RANK, (long long)VDIM, 1.0f, 0, 1);

    // 8) out = o @ wo^T : f16 2-term, fp32 out
    gemm_f16<<<dim3(HID / 128, TT / 128, 1), 256, 3 * 3 * PART>>>(
        o_h, o_l, wo16, out, nullptr, nullptr,
        H * VDIM, H * VDIM, H * VDIM, HID, 0, 0, 0, 1.0f, 0, 1);
}

// round 15
// speedup vs baseline: 1.7571x; 1.0921x over previous
#include <cuda_runtime.h>
#include <cuda_bf16.h>
#include <cuda_fp16.h>
#include <stdint.h>
#include <math.h>

// ---------------- problem constants ----------------
#define TT    2048
#define H     16
#define NOPE  128
#define ROPE  64
#define VDIM  128
#define RANK  512
#define QIN   1536
#define HID   7168
#define DQK   576
#define DS    192
#define QFW   (H * (NOPE + ROPE))   // 3072

typedef __nv_bfloat16 bf16;

// fp32 intermediates
static __device__ float g_qf[(size_t)TT * QFW];

// bf16 hi/lo pairs
static __device__ bf16 g_q_h  [(size_t)TT * QIN],      g_q_l  [(size_t)TT * QIN];
static __device__ bf16 g_wq_h [(size_t)QFW * QIN],     g_wq_l [(size_t)QFW * QIN];
static __device__ bf16 g_kc_h [(size_t)TT * DQK],      g_kc_l [(size_t)TT * DQK];
static __device__ bf16 g_kvb_h[(size_t)H * 256 * RANK], g_kvb_l[(size_t)H * 256 * RANK];
static __device__ bf16 g_ol_h [(size_t)TT * H * RANK], g_ol_l [(size_t)TT * H * RANK];

// fp16 operands
static __device__ __half g_qf16_h[(size_t)TT * QFW], g_qf16_l[(size_t)TT * QFW]; // qf pairs
static __device__ __half g_kc2f  [(size_t)H * TT * DS];                          // [k_up|k_pe_r] hi
static __device__ __half g_Sp_h  [(size_t)H * TT * TT];                          // scores->probs hi
static __device__ __half g_kT16  [(size_t)RANK * TT];
static __device__ __half g_o_h   [(size_t)TT * H * VDIM], g_o_l[(size_t)TT * H * VDIM];
static __device__ __half g_wo16  [(size_t)HID * H * VDIM];

// ---------------- ptx helpers ----------------
#define MMA_BF16(C, A, B0, B1)                                              \
    asm volatile(                                                           \
        "mma.sync.aligned.m16n8k16.row.col.f32.bf16.bf16.f32 "              \
        "{%0,%1,%2,%3},{%4,%5,%6,%7},{%8,%9},{%0,%1,%2,%3};\n"              \
        : "+f"(C[0]), "+f"(C[1]), "+f"(C[2]), "+f"(C[3])                    \
        : "r"(A[0]), "r"(A[1]), "r"(A[2]), "r"(A[3]), "r"(B0), "r"(B1));

#define MMA_F16(C, A, B0, B1)                                               \
    asm volatile(                                                           \
        "mma.sync.aligned.m16n8k16.row.col.f32.f16.f16.f32 "                \
        "{%0,%1,%2,%3},{%4,%5,%6,%7},{%8,%9},{%0,%1,%2,%3};\n"              \
        : "+f"(C[0]), "+f"(C[1]), "+f"(C[2]), "+f"(C[3])                    \
        : "r"(A[0]), "r"(A[1]), "r"(A[2]), "r"(A[3]), "r"(B0), "r"(B1));

#define LDSM_X4(R0, R1, R2, R3, ADDR)                                       \
    asm volatile("ldmatrix.sync.aligned.m8n8.x4.shared.b16 {%0,%1,%2,%3}, [%4];" \
        : "=r"(R0), "=r"(R1), "=r"(R2), "=r"(R3) : "r"(ADDR));

#define CP16(SM, G) asm volatile("cp.async.cg.shared.global [%0], [%1], 16;\n" :: "r"(SM), "l"(G))
#define CP_COMMIT   asm volatile("cp.async.commit_group;\n")
#define CP_WAIT0    asm volatile("cp.async.wait_group 0;\n")
#define CP_WAIT1    asm volatile("cp.async.wait_group 1;\n")

__device__ __forceinline__ void wr_pair(bf16* hi, bf16* lo, long long idx, float v) {
    bf16 h = __float2bfloat16(v);
    hi[idx] = h;
    lo[idx] = __float2bfloat16(v - __bfloat162float(h));
}
__device__ __forceinline__ void wr_pair16(__half* hi, __half* lo, long long idx, float v) {
    __half h = __float2half(v);
    hi[idx] = h;
    lo[idx] = __float2half(v - __half2float(h));
}

#define KT       32
#define PART     8192
#define BUF_SZ   32768          // bf16x3: 4 parts
#define SM_BF    98304
#define SM_F16MAX 73728

// ---------------- bf16x3 tensor-core GEMM (2 CTAs/SM, 3-stage) ----------------
// pfp16: 0 = bf16 pairs out; 1 = fp16 pairs out; 2 = fp16 HI ONLY out.
__global__ __launch_bounds__(256, 2)
void gemm_cp(const bf16* __restrict__ Ahi, const bf16* __restrict__ Alo,
             const bf16* __restrict__ Bhi, const bf16* __restrict__ Blo,
             float* __restrict__ Cfp, bf16* __restrict__ Chi, bf16* __restrict__ Clo,
             int K, int sa, int sb, int sc,
             long long aBS, long long bBS, long long cBS,
             float alpha, int mode, int pfp16)
{
    extern __shared__ char sm[];

    const int m0 = blockIdx.y * 128;
    const int n0 = blockIdx.x * 128;
    if ((mode & 1) && n0 > m0) return;
    int Keff = K;
    if (mode & 2) { int kl = m0 + 128; if (kl < Keff) Keff = kl; }

    Ahi += (long long)blockIdx.z * aBS + (long long)m0 * sa;
    Alo += (long long)blockIdx.z * aBS + (long long)m0 * sa;
    Bhi += (long long)blockIdx.z * bBS + (long long)n0 * sb;
    Blo += (long long)blockIdx.z * bBS + (long long)n0 * sb;
    const long long cOff = (long long)blockIdx.z * cBS + (long long)m0 * sc + n0;

    const int tid  = threadIdx.x;
    const int lane = tid & 31;
    const int wid  = tid >> 5;
    const int warpM = (wid & 3) * 32;
    const int warpN = (wid >> 2) * 64;
    const int srow  = tid >> 1;
    const int sch0  = (tid & 1) * 2;

    const uint32_t smBase = (uint32_t)__cvta_generic_to_shared(sm);

    float acc[2][8][4];
#pragma unroll
    for (int mi = 0; mi < 2; mi++)
#pragma unroll
        for (int ni = 0; ni < 8; ni++)
#pragma unroll
            for (int j = 0; j < 4; j++) acc[mi][ni][j] = 0.0f;

    auto issueTile = [&](int t) {
        const int kt = t * KT;
        const uint32_t sb0 = smBase + (t % 3) * BUF_SZ;
        const bf16* srcs[4] = {
            Ahi + (long long)srow * sa + kt,
            Alo + (long long)srow * sa + kt,
            Bhi + (long long)srow * sb + kt,
            Blo + (long long)srow * sb + kt };
        const int sw = (srow >> 1) & 3;
#pragma unroll
        for (int p = 0; p < 4; p++) {
            const uint32_t pb = sb0 + p * PART + srow * 64;
#pragma unroll
            for (int i = 0; i < 2; i++) {
                int ch = sch0 + i;
                CP16(pb + ((ch ^ sw) << 4), srcs[p] + ch * 8);
            }
        }
    };

    const int nT = Keff / KT;
    issueTile(0); CP_COMMIT;
    issueTile(1); CP_COMMIT;

    for (int t = 0; t < nT; t++) {
        if (t + 1 < nT) { CP_WAIT1; } else { CP_WAIT0; }
        __syncthreads();

        if (t + 2 < nT) { issueTile(t + 2); CP_COMMIT; }

        const uint32_t aHi = smBase + (t % 3) * BUF_SZ;
        const uint32_t aLo = aHi + PART;
        const uint32_t bHi = aLo + PART;
        const uint32_t bLo = bHi + PART;

#pragma unroll
        for (int ks = 0; ks < 2; ks++) {
            uint32_t ah[2][4], al[2][4];
            {
                const int lr = lane & 15;
                const int lc = lane >> 4;
#pragma unroll
                for (int mi = 0; mi < 2; mi++) {
                    int r  = warpM + mi * 16 + lr;
                    int ch = 2 * ks + lc;
                    uint32_t off = r * 64 + ((ch ^ ((r >> 1) & 3)) << 4);
                    LDSM_X4(ah[mi][0], ah[mi][1], ah[mi][2], ah[mi][3], aHi + off);
                    LDSM_X4(al[mi][0], al[mi][1], al[mi][2], al[mi][3], aLo + off);
                }
            }
            const int bn = (lane & 7) + ((lane >> 4) << 3);
            const int bc = 2 * ks + ((lane >> 3) & 1);
#pragma unroll
            for (int p = 0; p < 4; p++) {
                int r = warpN + p * 16 + bn;
                uint32_t off = r * 64 + ((bc ^ ((r >> 1) & 3)) << 4);
                uint32_t bh0, bh1, bh2, bh3, bl0, bl1, bl2, bl3;
                LDSM_X4(bh0, bh1, bh2, bh3, bHi + off);
                LDSM_X4(bl0, bl1, bl2, bl3, bLo + off);
#pragma unroll
                for (int mi = 0; mi < 2; mi++) {
                    MMA_BF16(acc[mi][2*p],   ah[mi], bh0, bh1);
                    MMA_BF16(acc[mi][2*p],   ah[mi], bl0, bl1);
                    MMA_BF16(acc[mi][2*p],   al[mi], bh0, bh1);
                    MMA_BF16(acc[mi][2*p+1], ah[mi], bh2, bh3);
                    MMA_BF16(acc[mi][2*p+1], ah[mi], bl2, bl3);
                    MMA_BF16(acc[mi][2*p+1], al[mi], bh2, bh3);
                }
            }
        }
    }

    // ---- epilogue ----
    const int g   = lane >> 2;
    const int tig = lane & 3;
#pragma unroll
    for (int mi = 0; mi < 2; mi++)
#pragma unroll
        for (int ni = 0; ni < 8; ni++) {
            int r  = warpM + mi * 16 + g;
            int cc = warpN + ni * 8 + 2 * tig;
            float v[4] = { alpha * acc[mi][ni][0], alpha * acc[mi][ni][1],
                           alpha * acc[mi][ni][2], alpha * acc[mi][ni][3] };
            long long i0 = cOff + (long long)r * sc + cc;
            long long i1 = cOff + (long long)(r + 8) * sc + cc;
            if (Cfp) {
                *(float2*)&Cfp[i0] = make_float2(v[0], v[1]);
                *(float2*)&Cfp[i1] = make_float2(v[2], v[3]);
            }
            if (Chi) {
                if (pfp16 == 2) {
                    __half* H16 = (__half*)Chi;
                    *(__half2*)&H16[i0] = __floats2half2_rn(v[0], v[1]);
                    *(__half2*)&H16[i1] = __floats2half2_rn(v[2], v[3]);
                } else if (pfp16 == 1) {
                    __half* H16 = (__half*)Chi;
                    __half* L16 = (__half*)Clo;
                    wr_pair16(H16, L16, i0, v[0]); wr_pair16(H16, L16, i0 + 1, v[1]);
                    wr_pair16(H16, L16, i1, v[2]); wr_pair16(H16, L16, i1 + 1, v[3]);
                } else {
                    wr_pair(Chi, Clo, i0, v[0]); wr_pair(Chi, Clo, i0 + 1, v[1]);
                    wr_pair(Chi, Clo, i1, v[2]); wr_pair(Chi, Clo, i1 + 1, v[3]);
                }
            }
        }
}

// ---------------- f16 tensor-core GEMM, 1 or 2 A-terms ----------------
// two=1: A = (Ahi + Alo), 2 MMAs/acc. two=0: A = Ahi only, 1 MMA/acc.
// outm: 0 = bf16 pairs out (Chi/Clo), 1 = fp16 HI only out (Chi cast).
__global__ __launch_bounds__(256, 2)
void gemm_f16(const __half* __restrict__ Ahi, const __half* __restrict__ Alo,
              const __half* __restrict__ Bhi,
              float* __restrict__ Cfp, bf16* __restrict__ Chi, bf16* __restrict__ Clo,
              int K, int sa, int sb, int sc,
              long long aBS, long long bBS, long long cBS,
              float alpha, int mode, int two, int outm)
{
    extern __shared__ char sm[];

    const int m0 = blockIdx.y * 128;
    const int n0 = blockIdx.x * 128;
    if ((mode & 1) && n0 > m0) return;
    int Keff = K;
    if (mode & 2) { int kl = m0 + 128; if (kl < Keff) Keff = kl; }

    Ahi += (long long)blockIdx.z * aBS + (long long)m0 * sa;
    Alo += (long long)blockIdx.z * aBS + (long long)m0 * sa;
    Bhi += (long long)blockIdx.z * bBS + (long long)n0 * sb;
    const long long cOff = (long long)blockIdx.z * cBS + (long long)m0 * sc + n0;

    const int tid  = threadIdx.x;
    const int lane = tid & 31;
    const int wid  = tid >> 5;
    const int warpM = (wid & 3) * 32;
    const int warpN = (wid >> 2) * 64;
    const int srow  = tid >> 1;
    const int sch0  = (tid & 1) * 2;

    const int nparts = two ? 3 : 2;
    const uint32_t BUF = nparts * PART;
    const uint32_t smBase = (uint32_t)__cvta_generic_to_shared(sm);

    float acc[2][8][4];
#pragma unroll
    for (int mi = 0; mi < 2; mi++)
#pragma unroll
        for (int ni = 0; ni < 8; ni++)
#pragma unroll
            for (int j = 0; j < 4; j++) acc[mi][ni][j] = 0.0f;

    auto issueTile = [&](int t) {
        const int kt = t * KT;
        const uint32_t sb0 = smBase + (t % 3) * BUF;
        const int sw = (srow >> 1) & 3;
        {
            const __half* g = Ahi + (long long)srow * sa + kt;
            const uint32_t pb = sb0 + srow * 64;
#pragma unroll
            for (int i = 0; i < 2; i++) {
                int ch = sch0 + i;
                CP16(pb + ((ch ^ sw) << 4), g + ch * 8);
            }
        }
        if (two) {
            const __half* g = Alo + (long long)srow * sa + kt;
            const uint32_t pb = sb0 + PART + srow * 64;
#pragma unroll
            for (int i = 0; i < 2; i++) {
                int ch = sch0 + i;
                CP16(pb + ((ch ^ sw) << 4), g + ch * 8);
            }
        }
        {
            const __half* g = Bhi + (long long)srow * sb + kt;
            const uint32_t pb = sb0 + (nparts - 1) * PART + srow * 64;
#pragma unroll
            for (int i = 0; i < 2; i++) {
                int ch = sch0 + i;
                CP16(pb + ((ch ^ sw) << 4), g + ch * 8);
            }
        }
    };

    const int nT = Keff / KT;
    issueTile(0); CP_COMMIT;
    issueTile(1); CP_COMMIT;

    for (int t = 0; t < nT; t++) {
        if (t + 1 < nT) { CP_WAIT1; } else { CP_WAIT0; }
        __syncthreads();

        if (t + 2 < nT) { issueTile(t + 2); CP_COMMIT; }

        const uint32_t aHi = smBase + (t % 3) * BUF;
        const uint32_t aLo = aHi + PART;
        const uint32_t bHi = aHi + (nparts - 1) * PART;

#pragma unroll
        for (int ks = 0; ks < 2; ks++) {
            uint32_t ah[2][4], al[2][4];
            {
                const int lr = lane & 15;
                const int lc = lane >> 4;
#pragma unroll
                for (int mi = 0; mi < 2; mi++) {
                    int r  = warpM + mi * 16 + lr;
                    int ch = 2 * ks + lc;
                    uint32_t off = r * 64 + ((ch ^ ((r >> 1) & 3)) << 4);
                    LDSM_X4(ah[mi][0], ah[mi][1], ah[mi][2], ah[mi][3], aHi + off);
                    if (two) LDSM_X4(al[mi][0], al[mi][1], al[mi][2], al[mi][3], aLo + off);
                }
            }
            const int bn = (lane & 7) + ((lane >> 4) << 3);
            const int bc = 2 * ks + ((lane >> 3) & 1);
#pragma unroll
            for (int p = 0; p < 4; p++) {
                int r = warpN + p * 16 + bn;
                uint32_t off = r * 64 + ((bc ^ ((r >> 1) & 3)) << 4);
                uint32_t bh0, bh1, bh2, bh3;
                LDSM_X4(bh0, bh1, bh2, bh3, bHi + off);
#pragma unroll
                for (int mi = 0; mi < 2; mi++) {
                    MMA_F16(acc[mi][2*p],   ah[mi], bh0, bh1);
                    MMA_F16(acc[mi][2*p+1], ah[mi], bh2, bh3);
                    if (two) {
                        MMA_F16(acc[mi][2*p],   al[mi], bh0, bh1);
                        MMA_F16(acc[mi][2*p+1], al[mi], bh2, bh3);
                    }
                }
            }
        }
    }

    // ---- epilogue ----
    const int g   = lane >> 2;
    const int tig = lane & 3;
#pragma unroll
    for (int mi = 0; mi < 2; mi++)
#pragma unroll
        for (int ni = 0; ni < 8; ni++) {
            int r  = warpM + mi * 16 + g;
            int cc = warpN + ni * 8 + 2 * tig;
            float v[4] = { alpha * acc[mi][ni][0], alpha * acc[mi][ni][1],
                           alpha * acc[mi][ni][2], alpha * acc[mi][ni][3] };
            long long i0 = cOff + (long long)r * sc + cc;
            long long i1 = cOff + (long long)(r + 8) * sc + cc;
            if (Cfp) {
                *(float2*)&Cfp[i0] = make_float2(v[0], v[1]);
                *(float2*)&Cfp[i1] = make_float2(v[2], v[3]);
            }
            if (Chi) {
                if (outm == 1) {
                    __half* H16 = (__half*)Chi;
                    *(__half2*)&H16[i0] = __floats2half2_rn(v[0], v[1]);
                    *(__half2*)&H16[i1] = __floats2half2_rn(v[2], v[3]);
                } else {
                    wr_pair(Chi, Clo, i0, v[0]); wr_pair(Chi, Clo, i0 + 1, v[1]);
                    wr_pair(Chi, Clo, i1, v[2]); wr_pair(Chi, Clo, i1 + 1, v[3]);
                }
            }
        }
}

// ---------------- conversion kernels ----------------
__global__ void cvt_pair(const float4* __restrict__ src,
                         __nv_bfloat162* __restrict__ hi, __nv_bfloat162* __restrict__ lo,
                         int n4)
{
    int i = blockIdx.x * 256 + threadIdx.x;
    if (i >= n4) return;
    float4 v = src[i];
    bf16 hx = __float2bfloat16(v.x), hy = __float2bfloat16(v.y);
    bf16 hz = __float2bfloat16(v.z), hw = __float2bfloat16(v.w);
    __nv_bfloat162 h0; h0.x = hx; h0.y = hy;
    __nv_bfloat162 h1; h1.x = hz; h1.y = hw;
    hi[2*i] = h0; hi[2*i+1] = h1;
    __nv_bfloat162 l0, l1;
    l0.x = __float2bfloat16(v.x - __bfloat162float(hx));
    l0.y = __float2bfloat16(v.y - __bfloat162float(hy));
    l1.x = __float2bfloat16(v.z - __bfloat162float(hz));
    l1.y = __float2bfloat16(v.w - __bfloat162float(hw));
    lo[2*i] = l0; lo[2*i+1] = l1;
}

__global__ void cvt_f16hi(const float4* __restrict__ src, __half2* __restrict__ hi, int n4)
{
    int i = blockIdx.x * 256 + threadIdx.x;
    if (i >= n4) return;
    float4 v = src[i];
    hi[2*i]   = __floats2half2_rn(v.x, v.y);
    hi[2*i+1] = __floats2half2_rn(v.z, v.w);
}

// dst[q][p] = src[p][q], fp16 hi only
__global__ void tr_cvt_f16(const float* __restrict__ src, __half* __restrict__ hi,
                           int P, int Q)
{
    __shared__ float t[32][33];
    const int p0 = blockIdx.y * 32, q0 = blockIdx.x * 32;
    t[threadIdx.y][threadIdx.x] = src[(long long)(p0 + threadIdx.y) * Q + q0 + threadIdx.x];
    __syncthreads();
    hi[(long long)(q0 + threadIdx.y) * P + p0 + threadIdx.x] =
        __float2half(t[threadIdx.x][threadIdx.y]);
}

// ---------------- RoPE + pack ----------------
__global__ void rope_pack(const float* __restrict__ qf, const float* __restrict__ k_c,
                          const float* __restrict__ k_pe, const int* __restrict__ pos,
                          const float* __restrict__ cosc, const float* __restrict__ sinc)
{
    int t = blockIdx.x;
    int p = pos[t];
    const float* cs = cosc + (long long)p * (ROPE / 2);
    const float* sn = sinc + (long long)p * (ROPE / 2);

    for (int i = threadIdx.x; i < RANK; i += blockDim.x)
        wr_pair(g_kc_h, g_kc_l, (long long)t * DQK + i, k_c[(long long)t * RANK + i]);

    for (int j = threadIdx.x; j < ROPE / 2; j += blockDim.x) {
        float x1 = k_pe[(long long)t * ROPE + j];
        float x2 = k_pe[(long long)t * ROPE + j + ROPE / 2];
        float c = cs[j], s = sn[j];
        __half h1 = __float2half(x1 * c - x2 * s);
        __half h2 = __float2half(x2 * c + x1 * s);
#pragma unroll
        for (int h = 0; h < H; h++) {
            long long base = ((long long)h * TT + t) * DS + NOPE;
            g_kc2f[base + j] = h1;
            g_kc2f[base + ROPE / 2 + j] = h2;
        }
    }

    for (int idx = threadIdx.x; idx < H * (ROPE / 2); idx += blockDim.x) {
        int h = idx / (ROPE / 2);
        int j = idx % (ROPE / 2);
        long long qb = (long long)t * QFW + h * DS + NOPE;
        float x1 = qf[qb + j];
        float x2 = qf[qb + ROPE / 2 + j];
        float c = cs[j], s = sn[j];
        wr_pair16(g_qf16_h, g_qf16_l, qb + j,            x1 * c - x2 * s);
        wr_pair16(g_qf16_h, g_qf16_l, qb + ROPE / 2 + j, x2 * c + x1 * s);
    }
}

// ---------------- causal softmax: fp16 hi in (scaled), fp16 hi out in-place ----------------
__global__ __launch_bounds__(256)
void softmax_causal(__half* __restrict__ Sh, const int* __restrict__ pos, float scale)
{
    const int t = blockIdx.x;
    const int h = blockIdx.y;
    const long long rb = ((long long)h * TT + t) * TT;
    const int pq = pos[t];
    const int limit = ((t >> 7) + 1) << 7;

    __shared__ float red[256];
    const int tid = threadIdx.x;

    float v[8];
    float m = -1e30f;
#pragma unroll
    for (int i = 0; i < 8; i++) {
        int s = tid + i * 256;
        v[i] = -1e30f;
        if (s < limit && pos[s] <= pq) v[i] = __half2float(Sh[rb + s]) * scale;
        m = fmaxf(m, v[i]);
    }
    red[tid] = m; __syncthreads();
    for (int w = 128; w > 0; w >>= 1) {
        if (tid < w) red[tid] = fmaxf(red[tid], red[tid + w]);
        __syncthreads();
    }
    m = red[0];
    __syncthreads();

    float sum = 0.0f;
#pragma unroll
    for (int i = 0; i < 8; i++) {
        v[i] = __expf(v[i] - m);
        sum += v[i];
    }
    red[tid] = sum; __syncthreads();
    for (int w = 128; w > 0; w >>= 1) {
        if (tid < w) red[tid] += red[tid + w];
        __syncthreads();
    }
    float inv = 1.0f / red[0];

#pragma unroll
    for (int i = 0; i < 8; i++) {
        int s = tid + i * 256;
        if (s < limit) Sh[rb + s] = __float2half(v[i] * inv);
    }
}

// ---------------- launch ----------------
extern "C" void kernel_launch(void* const* d_in, const int* in_sizes, int n_in,
                              void* d_out, int out_size)
{
    const float* q     = (const float*)d_in[0];
    const float* k_c   = (const float*)d_in[1];
    const float* k_pe  = (const float*)d_in[2];
    const int*   pos   = (const int*)  d_in[3];
    const float* wq    = (const float*)d_in[4];
    const float* kv_b  = (const float*)d_in[5];
    const float* wo    = (const float*)d_in[6];
    const float* cosc  = (const float*)d_in[7];
    const float* sinc  = (const float*)d_in[8];
    float* out = (float*)d_out;

    float *qf;
    cudaGetSymbolAddress((void**)&qf, g_qf);
    bf16 *q_h,*q_l,*wq_h,*wq_l,*kc_h,*kc_l,*kvb_h,*kvb_l,*ol_h,*ol_l;
    __half *qf16_h,*qf16_l,*kc2f,*Sp_h,*kT16,*o_h,*o_l,*wo16;
    cudaGetSymbolAddress((void**)&q_h,  g_q_h);  cudaGetSymbolAddress((void**)&q_l,  g_q_l);
    cudaGetSymbolAddress((void**)&wq_h, g_wq_h); cudaGetSymbolAddress((void**)&wq_l, g_wq_l);
    cudaGetSymbolAddress((void**)&kc_h, g_kc_h); cudaGetSymbolAddress((void**)&kc_l, g_kc_l);
    cudaGetSymbolAddress((void**)&kvb_h,g_kvb_h);cudaGetSymbolAddress((void**)&kvb_l,g_kvb_l);
    cudaGetSymbolAddress((void**)&ol_h, g_ol_h); cudaGetSymbolAddress((void**)&ol_l, g_ol_l);
    cudaGetSymbolAddress((void**)&qf16_h, g_qf16_h); cudaGetSymbolAddress((void**)&qf16_l, g_qf16_l);
    cudaGetSymbolAddress((void**)&kc2f, g_kc2f);
    cudaGetSymbolAddress((void**)&Sp_h, g_Sp_h);
    cudaGetSymbolAddress((void**)&kT16, g_kT16);
    cudaGetSymbolAddress((void**)&o_h,  g_o_h);  cudaGetSymbolAddress((void**)&o_l,  g_o_l);
    cudaGetSymbolAddress((void**)&wo16, g_wo16);

    cudaFuncSetAttribute(gemm_cp,  cudaFuncAttributeMaxDynamicSharedMemorySize, SM_BF);
    cudaFuncSetAttribute(gemm_f16, cudaFuncAttributeMaxDynamicSharedMemorySize, SM_F16MAX);

    const float scale = rsqrtf((float)(NOPE + ROPE));

    // ---- operand preconversion ----
    {
        int n4;
        n4 = TT * QIN / 4;
        cvt_pair<<<(n4 + 255) / 256, 256>>>((const float4*)q,  (__nv_bfloat162*)q_h,  (__nv_bfloat162*)q_l,  n4);
        n4 = QFW * QIN / 4;
        cvt_pair<<<(n4 + 255) / 256, 256>>>((const float4*)wq, (__nv_bfloat162*)wq_h, (__nv_bfloat162*)wq_l, n4);
        n4 = H * 256 * RANK / 4;
        cvt_pair<<<(n4 + 255) / 256, 256>>>((const float4*)kv_b, (__nv_bfloat162*)kvb_h, (__nv_bfloat162*)kvb_l, n4);
        n4 = HID * H * VDIM / 4;
        cvt_f16hi<<<(n4 + 255) / 256, 256>>>((const float4*)wo, (__half2*)wo16, n4);
        tr_cvt_f16<<<dim3(RANK / 32, TT / 32, 1), dim3(32, 32)>>>(k_c, kT16, TT, RANK);
    }

    // 1) qf = q @ wq^T  (bf16x3; fp32 qf + fp16 pairs in qc2 layout)
    gemm_cp<<<dim3(QFW / 128, TT / 128, 1), 256, SM_BF>>>(
        q_h, q_l, wq_h, wq_l, qf, (bf16*)qf16_h, (bf16*)qf16_l,
        QIN, QIN, QIN, QFW, 0, 0, 0, 1.0f, 0, 1);

    // 2) rope + pack
    rope_pack<<<TT, 256>>>(qf, k_c, k_pe, pos, cosc, sinc);

    // 3) k_up_h = k_c @ w_uk_h  (bf16x3; fp16 HI out -> kc2f[:,0:128])
    gemm_cp<<<dim3(1, TT / 128, H), 256, SM_BF>>>(
        kc_h, kc_l, kvb_h, kvb_l, nullptr, (bf16*)kc2f, nullptr,
        RANK, DQK, RANK, DS,
        0, (long long)256 * RANK, (long long)TT * DS, 1.0f, 0, 2);

    // 4) S_h = Qf16_h @ Kc2f_h^T : fp16x2 (A pair, B hi), K=192, causal skip, fp16 HI out
    gemm_f16<<<dim3(TT / 128, TT / 128, H), 256, 3 * 3 * PART>>>(
        qf16_h, qf16_l, kc2f, nullptr, (bf16*)Sp_h, nullptr,
        DS, QFW, DS, TT,
        (long long)DS, (long long)TT * DS, (long long)TT * TT, 1.0f, 1, 1, 1);

    // 5) softmax in-place on fp16 hi (scale on load)
    softmax_causal<<<dim3(TT, H), 256>>>(Sp_h, pos, scale);

    // 6) olat_h = P_h @ k_c : f16 1-term, K limited to m0+128, bf16 pairs out
    gemm_f16<<<dim3(RANK / 128, TT / 128, H), 256, 3 * 2 * PART>>>(
        Sp_h, Sp_h, kT16, nullptr, ol_h, ol_l,
        TT, TT, TT, H * RANK,
        (long long)TT * TT, 0, (long long)RANK, 1.0f, 2, 0, 0);

    // 7) o_h = olat_h @ w_uv_h : bf16x3, fp16 pairs out
    gemm_cp<<<dim3(VDIM / 128, TT / 128, H), 256, SM_BF>>>(
        ol_h, ol_l, kvb_h + (long long)NOPE * RANK, kvb_l + (long long)NOPE * RANK,
        nullptr, (bf16*)o_h, (bf16*)o_l,
        RANK, H * RANK, RANK, H * VDIM,
        (long long)RANK, (long long)256 * RANK, (long long)VDIM, 1.0f, 0, 1);

    // 8) out = o @ wo^T : f16 1-term (o hi only), fp32 out
    gemm_f16<<<dim3(HID / 128, TT / 128, 1), 256, 3 * 2 * PART>>>(
        o_h, o_h, wo16, out, nullptr, nullptr,
        H * VDIM, H * VDIM, H * VDIM, HID, 0, 0, 0, 1.0f, 0, 0, 0);
}

// round 16
// speedup vs baseline: 1.9164x; 1.0906x over previous
#include <cuda_runtime.h>
#include <cuda_fp16.h>
#include <stdint.h>
#include <math.h>

// ---------------- problem constants ----------------
#define TT    2048
#define H     16
#define NOPE  128
#define ROPE  64
#define VDIM  128
#define RANK  512
#define QIN   1536
#define HID   7168
#define DS    192
#define QFW   (H * (NOPE + ROPE))   // 3072

// fp32 intermediates
static __device__ float g_qf[(size_t)TT * QFW];

// fp16 operands
static __device__ __half g_q16_h [(size_t)TT * QIN],   g_q16_l [(size_t)TT * QIN];
static __device__ __half g_wq16  [(size_t)QFW * QIN];
static __device__ __half g_qf16_h[(size_t)TT * QFW],   g_qf16_l[(size_t)TT * QFW];
static __device__ __half g_kc16_h[(size_t)TT * RANK],  g_kc16_l[(size_t)TT * RANK];
static __device__ __half g_kvb16 [(size_t)H * 256 * RANK];
static __device__ __half g_kc2f  [(size_t)H * TT * DS];
static __device__ __half g_Sp_h  [(size_t)H * TT * TT];
static __device__ __half g_kT16  [(size_t)RANK * TT];
static __device__ __half g_ol16_h[(size_t)TT * H * RANK], g_ol16_l[(size_t)TT * H * RANK];
static __device__ __half g_o_h   [(size_t)TT * H * VDIM];
static __device__ __half g_wo16  [(size_t)HID * H * VDIM];

// ---------------- ptx helpers ----------------
#define MMA_F16(C, A, B0, B1)                                               \
    asm volatile(                                                           \
        "mma.sync.aligned.m16n8k16.row.col.f32.f16.f16.f32 "                \
        "{%0,%1,%2,%3},{%4,%5,%6,%7},{%8,%9},{%0,%1,%2,%3};\n"              \
        : "+f"(C[0]), "+f"(C[1]), "+f"(C[2]), "+f"(C[3])                    \
        : "r"(A[0]), "r"(A[1]), "r"(A[2]), "r"(A[3]), "r"(B0), "r"(B1));

#define LDSM_X4(R0, R1, R2, R3, ADDR)                                       \
    asm volatile("ldmatrix.sync.aligned.m8n8.x4.shared.b16 {%0,%1,%2,%3}, [%4];" \
        : "=r"(R0), "=r"(R1), "=r"(R2), "=r"(R3) : "r"(ADDR));

#define CP16(SM, G) asm volatile("cp.async.cg.shared.global [%0], [%1], 16;\n" :: "r"(SM), "l"(G))
#define CP_COMMIT   asm volatile("cp.async.commit_group;\n")
#define CP_WAIT0    asm volatile("cp.async.wait_group 0;\n")
#define CP_WAIT1    asm volatile("cp.async.wait_group 1;\n")

__device__ __forceinline__ void wr_pair16(__half* hi, __half* lo, long long idx, float v) {
    __half h = __float2half(v);
    hi[idx] = h;
    lo[idx] = __float2half(v - __half2float(h));
}

#define KT       32
#define PART     8192
#define SM_MAX   73728   // 3 parts x 3 stages

// ---------------- fp16 tensor-core GEMM (2 CTAs/SM, 3-stage) ----------------
// two=1: A = (Ahi + Alo) pair, 2 MMAs/acc. two=0: A = Ahi only, 1 MMA/acc.
// outm: 1 = fp16 HI only out; 2 = fp16 pairs out; 0 = none (Cfp only).
__global__ __launch_bounds__(256, 2)
void gemm_f16(const __half* __restrict__ Ahi, const __half* __restrict__ Alo,
              const __half* __restrict__ Bhi,
              float* __restrict__ Cfp, __half* __restrict__ Chi, __half* __restrict__ Clo,
              int K, int sa, int sb, int sc,
              long long aBS, long long bBS, long long cBS,
              float alpha, int mode, int two, int outm)
{
    extern __shared__ char sm[];

    const int m0 = blockIdx.y * 128;
    const int n0 = blockIdx.x * 128;
    if ((mode & 1) && n0 > m0) return;
    int Keff = K;
    if (mode & 2) { int kl = m0 + 128; if (kl < Keff) Keff = kl; }

    Ahi += (long long)blockIdx.z * aBS + (long long)m0 * sa;
    Alo += (long long)blockIdx.z * aBS + (long long)m0 * sa;
    Bhi += (long long)blockIdx.z * bBS + (long long)n0 * sb;
    const long long cOff = (long long)blockIdx.z * cBS + (long long)m0 * sc + n0;

    const int tid  = threadIdx.x;
    const int lane = tid & 31;
    const int wid  = tid >> 5;
    const int warpM = (wid & 3) * 32;
    const int warpN = (wid >> 2) * 64;
    const int srow  = tid >> 1;
    const int sch0  = (tid & 1) * 2;

    const int nparts = two ? 3 : 2;
    const uint32_t BUF = nparts * PART;
    const uint32_t smBase = (uint32_t)__cvta_generic_to_shared(sm);

    float acc[2][8][4];
#pragma unroll
    for (int mi = 0; mi < 2; mi++)
#pragma unroll
        for (int ni = 0; ni < 8; ni++)
#pragma unroll
            for (int j = 0; j < 4; j++) acc[mi][ni][j] = 0.0f;

    auto issueTile = [&](int t) {
        const int kt = t * KT;
        const uint32_t sb0 = smBase + (t % 3) * BUF;
        const int sw = (srow >> 1) & 3;
        {
            const __half* g = Ahi + (long long)srow * sa + kt;
            const uint32_t pb = sb0 + srow * 64;
#pragma unroll
            for (int i = 0; i < 2; i++) {
                int ch = sch0 + i;
                CP16(pb + ((ch ^ sw) << 4), g + ch * 8);
            }
        }
        if (two) {
            const __half* g = Alo + (long long)srow * sa + kt;
            const uint32_t pb = sb0 + PART + srow * 64;
#pragma unroll
            for (int i = 0; i < 2; i++) {
                int ch = sch0 + i;
                CP16(pb + ((ch ^ sw) << 4), g + ch * 8);
            }
        }
        {
            const __half* g = Bhi + (long long)srow * sb + kt;
            const uint32_t pb = sb0 + (nparts - 1) * PART + srow * 64;
#pragma unroll
            for (int i = 0; i < 2; i++) {
                int ch = sch0 + i;
                CP16(pb + ((ch ^ sw) << 4), g + ch * 8);
            }
        }
    };

    const int nT = Keff / KT;
    issueTile(0); CP_COMMIT;
    issueTile(1); CP_COMMIT;

    for (int t = 0; t < nT; t++) {
        if (t + 1 < nT) { CP_WAIT1; } else { CP_WAIT0; }
        __syncthreads();

        if (t + 2 < nT) { issueTile(t + 2); CP_COMMIT; }

        const uint32_t aHi = smBase + (t % 3) * BUF;
        const uint32_t aLo = aHi + PART;
        const uint32_t bHi = aHi + (nparts - 1) * PART;

#pragma unroll
        for (int ks = 0; ks < 2; ks++) {
            uint32_t ah[2][4], al[2][4];
            {
                const int lr = lane & 15;
                const int lc = lane >> 4;
#pragma unroll
                for (int mi = 0; mi < 2; mi++) {
                    int r  = warpM + mi * 16 + lr;
                    int ch = 2 * ks + lc;
                    uint32_t off = r * 64 + ((ch ^ ((r >> 1) & 3)) << 4);
                    LDSM_X4(ah[mi][0], ah[mi][1], ah[mi][2], ah[mi][3], aHi + off);
                    if (two) LDSM_X4(al[mi][0], al[mi][1], al[mi][2], al[mi][3], aLo + off);
                }
            }
            const int bn = (lane & 7) + ((lane >> 4) << 3);
            const int bc = 2 * ks + ((lane >> 3) & 1);
#pragma unroll
            for (int p = 0; p < 4; p++) {
                int r = warpN + p * 16 + bn;
                uint32_t off = r * 64 + ((bc ^ ((r >> 1) & 3)) << 4);
                uint32_t bh0, bh1, bh2, bh3;
                LDSM_X4(bh0, bh1, bh2, bh3, bHi + off);
#pragma unroll
                for (int mi = 0; mi < 2; mi++) {
                    MMA_F16(acc[mi][2*p],   ah[mi], bh0, bh1);
                    MMA_F16(acc[mi][2*p+1], ah[mi], bh2, bh3);
                    if (two) {
                        MMA_F16(acc[mi][2*p],   al[mi], bh0, bh1);
                        MMA_F16(acc[mi][2*p+1], al[mi], bh2, bh3);
                    }
                }
            }
        }
    }

    // ---- epilogue ----
    const int g   = lane >> 2;
    const int tig = lane & 3;
#pragma unroll
    for (int mi = 0; mi < 2; mi++)
#pragma unroll
        for (int ni = 0; ni < 8; ni++) {
            int r  = warpM + mi * 16 + g;
            int cc = warpN + ni * 8 + 2 * tig;
            float v[4] = { alpha * acc[mi][ni][0], alpha * acc[mi][ni][1],
                           alpha * acc[mi][ni][2], alpha * acc[mi][ni][3] };
            long long i0 = cOff + (long long)r * sc + cc;
            long long i1 = cOff + (long long)(r + 8) * sc + cc;
            if (Cfp) {
                *(float2*)&Cfp[i0] = make_float2(v[0], v[1]);
                *(float2*)&Cfp[i1] = make_float2(v[2], v[3]);
            }
            if (outm == 1) {
                *(__half2*)&Chi[i0] = __floats2half2_rn(v[0], v[1]);
                *(__half2*)&Chi[i1] = __floats2half2_rn(v[2], v[3]);
            } else if (outm == 2) {
                wr_pair16(Chi, Clo, i0, v[0]); wr_pair16(Chi, Clo, i0 + 1, v[1]);
                wr_pair16(Chi, Clo, i1, v[2]); wr_pair16(Chi, Clo, i1 + 1, v[3]);
            }
        }
}

// ---------------- conversion kernels ----------------
__global__ void cvt_f16pair(const float4* __restrict__ src,
                            __half2* __restrict__ hi, __half2* __restrict__ lo, int n4)
{
    int i = blockIdx.x * 256 + threadIdx.x;
    if (i >= n4) return;
    float4 v = src[i];
    __half2 h0 = __floats2half2_rn(v.x, v.y);
    __half2 h1 = __floats2half2_rn(v.z, v.w);
    hi[2*i] = h0; hi[2*i+1] = h1;
    lo[2*i]   = __floats2half2_rn(v.x - __low2float(h0),  v.y - __high2float(h0));
    lo[2*i+1] = __floats2half2_rn(v.z - __low2float(h1),  v.w - __high2float(h1));
}

__global__ void cvt_f16hi(const float4* __restrict__ src, __half2* __restrict__ hi, int n4)
{
    int i = blockIdx.x * 256 + threadIdx.x;
    if (i >= n4) return;
    float4 v = src[i];
    hi[2*i]   = __floats2half2_rn(v.x, v.y);
    hi[2*i+1] = __floats2half2_rn(v.z, v.w);
}

// dst[q][p] = src[p][q], fp16 hi only
__global__ void tr_cvt_f16(const float* __restrict__ src, __half* __restrict__ hi,
                           int P, int Q)
{
    __shared__ float t[32][33];
    const int p0 = blockIdx.y * 32, q0 = blockIdx.x * 32;
    t[threadIdx.y][threadIdx.x] = src[(long long)(p0 + threadIdx.y) * Q + q0 + threadIdx.x];
    __syncthreads();
    hi[(long long)(q0 + threadIdx.y) * P + p0 + threadIdx.x] =
        __float2half(t[threadIdx.x][threadIdx.y]);
}

// ---------------- RoPE + pack ----------------
__global__ void rope_pack(const float* __restrict__ qf, const float* __restrict__ k_pe,
                          const int* __restrict__ pos,
                          const float* __restrict__ cosc, const float* __restrict__ sinc)
{
    int t = blockIdx.x;
    int p = pos[t];
    const float* cs = cosc + (long long)p * (ROPE / 2);
    const float* sn = sinc + (long long)p * (ROPE / 2);

    for (int j = threadIdx.x; j < ROPE / 2; j += blockDim.x) {
        float x1 = k_pe[(long long)t * ROPE + j];
        float x2 = k_pe[(long long)t * ROPE + j + ROPE / 2];
        float c = cs[j], s = sn[j];
        __half h1 = __float2half(x1 * c - x2 * s);
        __half h2 = __float2half(x2 * c + x1 * s);
#pragma unroll
        for (int h = 0; h < H; h++) {
            long long base = ((long long)h * TT + t) * DS + NOPE;
            g_kc2f[base + j] = h1;
            g_kc2f[base + ROPE / 2 + j] = h2;
        }
    }

    for (int idx = threadIdx.x; idx < H * (ROPE / 2); idx += blockDim.x) {
        int h = idx / (ROPE / 2);
        int j = idx % (ROPE / 2);
        long long qb = (long long)t * QFW + h * DS + NOPE;
        float x1 = qf[qb + j];
        float x2 = qf[qb + ROPE / 2 + j];
        float c = cs[j], s = sn[j];
        wr_pair16(g_qf16_h, g_qf16_l, qb + j,            x1 * c - x2 * s);
        wr_pair16(g_qf16_h, g_qf16_l, qb + ROPE / 2 + j, x2 * c + x1 * s);
    }
}

// ---------------- causal softmax: fp16 hi in (scaled), fp16 hi out in-place ----------------
__global__ __launch_bounds__(256)
void softmax_causal(__half* __restrict__ Sh, const int* __restrict__ pos, float scale)
{
    const int t = blockIdx.x;
    const int h = blockIdx.y;
    const long long rb = ((long long)h * TT + t) * TT;
    const int pq = pos[t];
    const int limit = ((t >> 7) + 1) << 7;

    __shared__ float red[256];
    const int tid = threadIdx.x;

    float v[8];
    float m = -1e30f;
#pragma unroll
    for (int i = 0; i < 8; i++) {
        int s = tid + i * 256;
        v[i] = -1e30f;
        if (s < limit && pos[s] <= pq) v[i] = __half2float(Sh[rb + s]) * scale;
        m = fmaxf(m, v[i]);
    }
    red[tid] = m; __syncthreads();
    for (int w = 128; w > 0; w >>= 1) {
        if (tid < w) red[tid] = fmaxf(red[tid], red[tid + w]);
        __syncthreads();
    }
    m = red[0];
    __syncthreads();

    float sum = 0.0f;
#pragma unroll
    for (int i = 0; i < 8; i++) {
        v[i] = __expf(v[i] - m);
        sum += v[i];
    }
    red[tid] = sum; __syncthreads();
    for (int w = 128; w > 0; w >>= 1) {
        if (tid < w) red[tid] += red[tid + w];
        __syncthreads();
    }
    float inv = 1.0f / red[0];

#pragma unroll
    for (int i = 0; i < 8; i++) {
        int s = tid + i * 256;
        if (s < limit) Sh[rb + s] = __float2half(v[i] * inv);
    }
}

// ---------------- launch ----------------
extern "C" void kernel_launch(void* const* d_in, const int* in_sizes, int n_in,
                              void* d_out, int out_size)
{
    const float* q     = (const float*)d_in[0];
    const float* k_c   = (const float*)d_in[1];
    const float* k_pe  = (const float*)d_in[2];
    const int*   pos   = (const int*)  d_in[3];
    const float* wq    = (const float*)d_in[4];
    const float* kv_b  = (const float*)d_in[5];
    const float* wo    = (const float*)d_in[6];
    const float* cosc  = (const float*)d_in[7];
    const float* sinc  = (const float*)d_in[8];
    float* out = (float*)d_out;

    float *qf;
    cudaGetSymbolAddress((void**)&qf, g_qf);
    __half *q16_h,*q16_l,*wq16,*qf16_h,*qf16_l,*kc16_h,*kc16_l,*kvb16,*kc2f;
    __half *Sp_h,*kT16,*ol16_h,*ol16_l,*o_h,*wo16;
    cudaGetSymbolAddress((void**)&q16_h,  g_q16_h);  cudaGetSymbolAddress((void**)&q16_l,  g_q16_l);
    cudaGetSymbolAddress((void**)&wq16,   g_wq16);
    cudaGetSymbolAddress((void**)&qf16_h, g_qf16_h); cudaGetSymbolAddress((void**)&qf16_l, g_qf16_l);
    cudaGetSymbolAddress((void**)&kc16_h, g_kc16_h); cudaGetSymbolAddress((void**)&kc16_l, g_kc16_l);
    cudaGetSymbolAddress((void**)&kvb16,  g_kvb16);
    cudaGetSymbolAddress((void**)&kc2f,   g_kc2f);
    cudaGetSymbolAddress((void**)&Sp_h,   g_Sp_h);
    cudaGetSymbolAddress((void**)&kT16,   g_kT16);
    cudaGetSymbolAddress((void**)&ol16_h, g_ol16_h); cudaGetSymbolAddress((void**)&ol16_l, g_ol16_l);
    cudaGetSymbolAddress((void**)&o_h,    g_o_h);
    cudaGetSymbolAddress((void**)&wo16,   g_wo16);

    cudaFuncSetAttribute(gemm_f16, cudaFuncAttributeMaxDynamicSharedMemorySize, SM_MAX);

    const float scale = rsqrtf((float)(NOPE + ROPE));

    // ---- operand preconversion ----
    {
        int n4;
        n4 = TT * QIN / 4;
        cvt_f16pair<<<(n4 + 255) / 256, 256>>>((const float4*)q, (__half2*)q16_h, (__half2*)q16_l, n4);
        n4 = QFW * QIN / 4;
        cvt_f16hi<<<(n4 + 255) / 256, 256>>>((const float4*)wq, (__half2*)wq16, n4);
        n4 = H * 256 * RANK / 4;
        cvt_f16hi<<<(n4 + 255) / 256, 256>>>((const float4*)kv_b, (__half2*)kvb16, n4);
        n4 = TT * RANK / 4;
        cvt_f16pair<<<(n4 + 255) / 256, 256>>>((const float4*)k_c, (__half2*)kc16_h, (__half2*)kc16_l, n4);
        n4 = HID * H * VDIM / 4;
        cvt_f16hi<<<(n4 + 255) / 256, 256>>>((const float4*)wo, (__half2*)wo16, n4);
        tr_cvt_f16<<<dim3(RANK / 32, TT / 32, 1), dim3(32, 32)>>>(k_c, kT16, TT, RANK);
    }

    // 1) qf = q @ wq^T : fp16 2-term; fp32 qf + fp16 pairs (qc2 layout)
    gemm_f16<<<dim3(QFW / 128, TT / 128, 1), 256, 3 * 3 * PART>>>(
        q16_h, q16_l, wq16, qf, qf16_h, qf16_l,
        QIN, QIN, QIN, QFW, 0, 0, 0, 1.0f, 0, 1, 2);

    // 2) rope + pack
    rope_pack<<<TT, 256>>>(qf, k_pe, pos, cosc, sinc);

    // 3) k_up_h = k_c @ w_uk_h : fp16 2-term, fp16 hi out -> kc2f[:,0:128]
    gemm_f16<<<dim3(1, TT / 128, H), 256, 3 * 3 * PART>>>(
        kc16_h, kc16_l, kvb16, nullptr, kc2f, nullptr,
        RANK, RANK, RANK, DS,
        0, (long long)256 * RANK, (long long)TT * DS, 1.0f, 0, 1, 1);

    // 4) S_h = Qf16_h @ Kc2f_h^T : fp16 2-term, K=192, causal skip, fp16 hi out
    gemm_f16<<<dim3(TT / 128, TT / 128, H), 256, 3 * 3 * PART>>>(
        qf16_h, qf16_l, kc2f, nullptr, Sp_h, nullptr,
        DS, QFW, DS, TT,
        (long long)DS, (long long)TT * DS, (long long)TT * TT, 1.0f, 1, 1, 1);

    // 5) softmax in-place (scale on load)
    softmax_causal<<<dim3(TT, H), 256>>>(Sp_h, pos, scale);

    // 6) olat_h = P_h @ k_c : fp16 1-term, K limited to m0+128, fp16 pairs out
    gemm_f16<<<dim3(RANK / 128, TT / 128, H), 256, 3 * 2 * PART>>>(
        Sp_h, Sp_h, kT16, nullptr, ol16_h, ol16_l,
        TT, TT, TT, H * RANK,
        (long long)TT * TT, 0, (long long)RANK, 1.0f, 2, 0, 2);

    // 7) o_h = olat_h @ w_uv_h : fp16 2-term, fp16 hi out
    gemm_f16<<<dim3(VDIM / 128, TT / 128, H), 256, 3 * 3 * PART>>>(
        ol16_h, ol16_l, kvb16 + (long long)NOPE * RANK, nullptr, o_h, nullptr,
        RANK, H * RANK, RANK, H * VDIM,
        (long long)RANK, (long long)256 * RANK, (long long)VDIM, 1.0f, 0, 1, 1);

    // 8) out = o @ wo^T : fp16 1-term, fp32 out
    gemm_f16<<<dim3(HID / 128, TT / 128, 1), 256, 3 * 2 * PART>>>(
        o_h, o_h, wo16, out, nullptr, nullptr,
        H * VDIM, H * VDIM, H * VDIM, HID, 0, 0, 0, 1.0f, 0, 0, 0);
}

// round 17
// speedup vs baseline: 2.2073x; 1.1518x over previous
#include <cuda_runtime.h>
#include <cuda_fp16.h>
#include <stdint.h>
#include <math.h>

// ---------------- problem constants ----------------
#define TT    2048
#define H     16
#define NOPE  128
#define ROPE  64
#define VDIM  128
#define RANK  512
#define QIN   1536
#define HID   7168
#define DS    192
#define QFW   (H * (NOPE + ROPE))   // 3072

// fp32 intermediates
static __device__ float g_qf[(size_t)TT * QFW];

// fp16 operands (hi-only pipeline)
static __device__ __half g_q16  [(size_t)TT * QIN];
static __device__ __half g_wq16 [(size_t)QFW * QIN];
static __device__ __half g_qf16 [(size_t)TT * QFW];
static __device__ __half g_kc16 [(size_t)TT * RANK];
static __device__ __half g_kvb16[(size_t)H * 256 * RANK];
static __device__ __half g_kc2f [(size_t)H * TT * DS];
static __device__ __half g_Sp_h [(size_t)H * TT * TT];
static __device__ __half g_kT16 [(size_t)RANK * TT];
static __device__ __half g_ol16 [(size_t)TT * H * RANK];
static __device__ __half g_o_h  [(size_t)TT * H * VDIM];
static __device__ __half g_wo16 [(size_t)HID * H * VDIM];

// ---------------- ptx helpers ----------------
#define MMA_F16(C, A, B0, B1)                                               \
    asm volatile(                                                           \
        "mma.sync.aligned.m16n8k16.row.col.f32.f16.f16.f32 "                \
        "{%0,%1,%2,%3},{%4,%5,%6,%7},{%8,%9},{%0,%1,%2,%3};\n"              \
        : "+f"(C[0]), "+f"(C[1]), "+f"(C[2]), "+f"(C[3])                    \
        : "r"(A[0]), "r"(A[1]), "r"(A[2]), "r"(A[3]), "r"(B0), "r"(B1));

#define LDSM_X4(R0, R1, R2, R3, ADDR)                                       \
    asm volatile("ldmatrix.sync.aligned.m8n8.x4.shared.b16 {%0,%1,%2,%3}, [%4];" \
        : "=r"(R0), "=r"(R1), "=r"(R2), "=r"(R3) : "r"(ADDR));

#define CP16(SM, G) asm volatile("cp.async.cg.shared.global [%0], [%1], 16;\n" :: "r"(SM), "l"(G))
#define CP_COMMIT   asm volatile("cp.async.commit_group;\n")
#define CP_WAIT0    asm volatile("cp.async.wait_group 0;\n")
#define CP_WAIT1    asm volatile("cp.async.wait_group 1;\n")

#define KT       32
#define PART     8192
#define SM_MAX   73728

// ---------------- fp16 tensor-core GEMM (2 CTAs/SM, 3-stage) ----------------
// two=1: A = (Ahi + Alo) pair. two=0: A = Ahi only.
// outm: 1 = fp16 HI out; 0 = none (Cfp only). (pairs no longer needed)
__global__ __launch_bounds__(256, 2)
void gemm_f16(const __half* __restrict__ Ahi, const __half* __restrict__ Alo,
              const __half* __restrict__ Bhi,
              float* __restrict__ Cfp, __half* __restrict__ Chi,
              int K, int sa, int sb, int sc,
              long long aBS, long long bBS, long long cBS,
              float alpha, int mode, int two, int outm)
{
    extern __shared__ char sm[];

    const int m0 = blockIdx.y * 128;
    const int n0 = blockIdx.x * 128;
    if ((mode & 1) && n0 > m0) return;
    int Keff = K;
    if (mode & 2) { int kl = m0 + 128; if (kl < Keff) Keff = kl; }

    Ahi += (long long)blockIdx.z * aBS + (long long)m0 * sa;
    Alo += (long long)blockIdx.z * aBS + (long long)m0 * sa;
    Bhi += (long long)blockIdx.z * bBS + (long long)n0 * sb;
    const long long cOff = (long long)blockIdx.z * cBS + (long long)m0 * sc + n0;

    const int tid  = threadIdx.x;
    const int lane = tid & 31;
    const int wid  = tid >> 5;
    const int warpM = (wid & 3) * 32;
    const int warpN = (wid >> 2) * 64;
    const int srow  = tid >> 1;
    const int sch0  = (tid & 1) * 2;

    const int nparts = two ? 3 : 2;
    const uint32_t BUF = nparts * PART;
    const uint32_t smBase = (uint32_t)__cvta_generic_to_shared(sm);

    float acc[2][8][4];
#pragma unroll
    for (int mi = 0; mi < 2; mi++)
#pragma unroll
        for (int ni = 0; ni < 8; ni++)
#pragma unroll
            for (int j = 0; j < 4; j++) acc[mi][ni][j] = 0.0f;

    auto issueTile = [&](int t) {
        const int kt = t * KT;
        const uint32_t sb0 = smBase + (t % 3) * BUF;
        const int sw = (srow >> 1) & 3;
        {
            const __half* g = Ahi + (long long)srow * sa + kt;
            const uint32_t pb = sb0 + srow * 64;
#pragma unroll
            for (int i = 0; i < 2; i++) {
                int ch = sch0 + i;
                CP16(pb + ((ch ^ sw) << 4), g + ch * 8);
            }
        }
        if (two) {
            const __half* g = Alo + (long long)srow * sa + kt;
            const uint32_t pb = sb0 + PART + srow * 64;
#pragma unroll
            for (int i = 0; i < 2; i++) {
                int ch = sch0 + i;
                CP16(pb + ((ch ^ sw) << 4), g + ch * 8);
            }
        }
        {
            const __half* g = Bhi + (long long)srow * sb + kt;
            const uint32_t pb = sb0 + (nparts - 1) * PART + srow * 64;
#pragma unroll
            for (int i = 0; i < 2; i++) {
                int ch = sch0 + i;
                CP16(pb + ((ch ^ sw) << 4), g + ch * 8);
            }
        }
    };

    const int nT = Keff / KT;
    issueTile(0); CP_COMMIT;
    issueTile(1); CP_COMMIT;

    for (int t = 0; t < nT; t++) {
        if (t + 1 < nT) { CP_WAIT1; } else { CP_WAIT0; }
        __syncthreads();

        if (t + 2 < nT) { issueTile(t + 2); CP_COMMIT; }

        const uint32_t aHi = smBase + (t % 3) * BUF;
        const uint32_t aLo = aHi + PART;
        const uint32_t bHi = aHi + (nparts - 1) * PART;

#pragma unroll
        for (int ks = 0; ks < 2; ks++) {
            uint32_t ah[2][4], al[2][4];
            {
                const int lr = lane & 15;
                const int lc = lane >> 4;
#pragma unroll
                for (int mi = 0; mi < 2; mi++) {
                    int r  = warpM + mi * 16 + lr;
                    int ch = 2 * ks + lc;
                    uint32_t off = r * 64 + ((ch ^ ((r >> 1) & 3)) << 4);
                    LDSM_X4(ah[mi][0], ah[mi][1], ah[mi][2], ah[mi][3], aHi + off);
                    if (two) LDSM_X4(al[mi][0], al[mi][1], al[mi][2], al[mi][3], aLo + off);
                }
            }
            const int bn = (lane & 7) + ((lane >> 4) << 3);
            const int bc = 2 * ks + ((lane >> 3) & 1);
#pragma unroll
            for (int p = 0; p < 4; p++) {
                int r = warpN + p * 16 + bn;
                uint32_t off = r * 64 + ((bc ^ ((r >> 1) & 3)) << 4);
                uint32_t bh0, bh1, bh2, bh3;
                LDSM_X4(bh0, bh1, bh2, bh3, bHi + off);
#pragma unroll
                for (int mi = 0; mi < 2; mi++) {
                    MMA_F16(acc[mi][2*p],   ah[mi], bh0, bh1);
                    MMA_F16(acc[mi][2*p+1], ah[mi], bh2, bh3);
                    if (two) {
                        MMA_F16(acc[mi][2*p],   al[mi], bh0, bh1);
                        MMA_F16(acc[mi][2*p+1], al[mi], bh2, bh3);
                    }
                }
            }
        }
    }

    // ---- epilogue ----
    const int g   = lane >> 2;
    const int tig = lane & 3;
#pragma unroll
    for (int mi = 0; mi < 2; mi++)
#pragma unroll
        for (int ni = 0; ni < 8; ni++) {
            int r  = warpM + mi * 16 + g;
            int cc = warpN + ni * 8 + 2 * tig;
            float v[4] = { alpha * acc[mi][ni][0], alpha * acc[mi][ni][1],
                           alpha * acc[mi][ni][2], alpha * acc[mi][ni][3] };
            long long i0 = cOff + (long long)r * sc + cc;
            long long i1 = cOff + (long long)(r + 8) * sc + cc;
            if (Cfp) {
                *(float2*)&Cfp[i0] = make_float2(v[0], v[1]);
                *(float2*)&Cfp[i1] = make_float2(v[2], v[3]);
            }
            if (outm == 1) {
                *(__half2*)&Chi[i0] = __floats2half2_rn(v[0], v[1]);
                *(__half2*)&Chi[i1] = __floats2half2_rn(v[2], v[3]);
            }
        }
}

// ---------------- conversion kernels ----------------
__global__ void cvt_f16hi(const float4* __restrict__ src, __half2* __restrict__ hi, int n4)
{
    int i = blockIdx.x * 256 + threadIdx.x;
    if (i >= n4) return;
    float4 v = src[i];
    hi[2*i]   = __floats2half2_rn(v.x, v.y);
    hi[2*i+1] = __floats2half2_rn(v.z, v.w);
}

// dst[q][p] = src[p][q], fp16 hi only
__global__ void tr_cvt_f16(const float* __restrict__ src, __half* __restrict__ hi,
                           int P, int Q)
{
    __shared__ float t[32][33];
    const int p0 = blockIdx.y * 32, q0 = blockIdx.x * 32;
    t[threadIdx.y][threadIdx.x] = src[(long long)(p0 + threadIdx.y) * Q + q0 + threadIdx.x];
    __syncthreads();
    hi[(long long)(q0 + threadIdx.y) * P + p0 + threadIdx.x] =
        __float2half(t[threadIdx.x][threadIdx.y]);
}

// ---------------- RoPE + pack ----------------
__global__ void rope_pack(const float* __restrict__ qf, const float* __restrict__ k_pe,
                          const int* __restrict__ pos,
                          const float* __restrict__ cosc, const float* __restrict__ sinc)
{
    int t = blockIdx.x;
    int p = pos[t];
    const float* cs = cosc + (long long)p * (ROPE / 2);
    const float* sn = sinc + (long long)p * (ROPE / 2);

    for (int j = threadIdx.x; j < ROPE / 2; j += blockDim.x) {
        float x1 = k_pe[(long long)t * ROPE + j];
        float x2 = k_pe[(long long)t * ROPE + j + ROPE / 2];
        float c = cs[j], s = sn[j];
        __half h1 = __float2half(x1 * c - x2 * s);
        __half h2 = __float2half(x2 * c + x1 * s);
#pragma unroll
        for (int h = 0; h < H; h++) {
            long long base = ((long long)h * TT + t) * DS + NOPE;
            g_kc2f[base + j] = h1;
            g_kc2f[base + ROPE / 2 + j] = h2;
        }
    }

    for (int idx = threadIdx.x; idx < H * (ROPE / 2); idx += blockDim.x) {
        int h = idx / (ROPE / 2);
        int j = idx % (ROPE / 2);
        long long qb = (long long)t * QFW + h * DS + NOPE;
        float x1 = qf[qb + j];
        float x2 = qf[qb + ROPE / 2 + j];
        float c = cs[j], s = sn[j];
        g_qf16[qb + j]            = __float2half(x1 * c - x2 * s);
        g_qf16[qb + ROPE / 2 + j] = __float2half(x2 * c + x1 * s);
    }
}

// ---------------- causal softmax: fp16 hi in (scaled), fp16 hi out in-place ----------------
__global__ __launch_bounds__(256)
void softmax_causal(__half* __restrict__ Sh, const int* __restrict__ pos, float scale)
{
    const int t = blockIdx.x;
    const int h = blockIdx.y;
    const long long rb = ((long long)h * TT + t) * TT;
    const int pq = pos[t];
    const int limit = ((t >> 7) + 1) << 7;

    __shared__ float red[256];
    const int tid = threadIdx.x;

    float v[8];
    float m = -1e30f;
#pragma unroll
    for (int i = 0; i < 8; i++) {
        int s = tid + i * 256;
        v[i] = -1e30f;
        if (s < limit && pos[s] <= pq) v[i] = __half2float(Sh[rb + s]) * scale;
        m = fmaxf(m, v[i]);
    }
    red[tid] = m; __syncthreads();
    for (int w = 128; w > 0; w >>= 1) {
        if (tid < w) red[tid] = fmaxf(red[tid], red[tid + w]);
        __syncthreads();
    }
    m = red[0];
    __syncthreads();

    float sum = 0.0f;
#pragma unroll
    for (int i = 0; i < 8; i++) {
        v[i] = __expf(v[i] - m);
        sum += v[i];
    }
    red[tid] = sum; __syncthreads();
    for (int w = 128; w > 0; w >>= 1) {
        if (tid < w) red[tid] += red[tid + w];
        __syncthreads();
    }
    float inv = 1.0f / red[0];

#pragma unroll
    for (int i = 0; i < 8; i++) {
        int s = tid + i * 256;
        if (s < limit) Sh[rb + s] = __float2half(v[i] * inv);
    }
}

// ---------------- launch ----------------
extern "C" void kernel_launch(void* const* d_in, const int* in_sizes, int n_in,
                              void* d_out, int out_size)
{
    const float* q     = (const float*)d_in[0];
    const float* k_c   = (const float*)d_in[1];
    const float* k_pe  = (const float*)d_in[2];
    const int*   pos   = (const int*)  d_in[3];
    const float* wq    = (const float*)d_in[4];
    const float* kv_b  = (const float*)d_in[5];
    const float* wo    = (const float*)d_in[6];
    const float* cosc  = (const float*)d_in[7];
    const float* sinc  = (const float*)d_in[8];
    float* out = (float*)d_out;

    float *qf;
    cudaGetSymbolAddress((void**)&qf, g_qf);
    __half *q16,*wq16,*qf16,*kc16,*kvb16,*kc2f,*Sp_h,*kT16,*ol16,*o_h,*wo16;
    cudaGetSymbolAddress((void**)&q16,  g_q16);
    cudaGetSymbolAddress((void**)&wq16, g_wq16);
    cudaGetSymbolAddress((void**)&qf16, g_qf16);
    cudaGetSymbolAddress((void**)&kc16, g_kc16);
    cudaGetSymbolAddress((void**)&kvb16,g_kvb16);
    cudaGetSymbolAddress((void**)&kc2f, g_kc2f);
    cudaGetSymbolAddress((void**)&Sp_h, g_Sp_h);
    cudaGetSymbolAddress((void**)&kT16, g_kT16);
    cudaGetSymbolAddress((void**)&ol16, g_ol16);
    cudaGetSymbolAddress((void**)&o_h,  g_o_h);
    cudaGetSymbolAddress((void**)&wo16, g_wo16);

    cudaFuncSetAttribute(gemm_f16, cudaFuncAttributeMaxDynamicSharedMemorySize, SM_MAX);

    const float scale = rsqrtf((float)(NOPE + ROPE));

    // ---- operand preconversion (all hi-only) ----
    {
        int n4;
        n4 = TT * QIN / 4;
        cvt_f16hi<<<(n4 + 255) / 256, 256>>>((const float4*)q, (__half2*)q16, n4);
        n4 = QFW * QIN / 4;
        cvt_f16hi<<<(n4 + 255) / 256, 256>>>((const float4*)wq, (__half2*)wq16, n4);
        n4 = H * 256 * RANK / 4;
        cvt_f16hi<<<(n4 + 255) / 256, 256>>>((const float4*)kv_b, (__half2*)kvb16, n4);
        n4 = TT * RANK / 4;
        cvt_f16hi<<<(n4 + 255) / 256, 256>>>((const float4*)k_c, (__half2*)kc16, n4);
        n4 = HID * H * VDIM / 4;
        cvt_f16hi<<<(n4 + 255) / 256, 256>>>((const float4*)wo, (__half2*)wo16, n4);
        tr_cvt_f16<<<dim3(RANK / 32, TT / 32, 1), dim3(32, 32)>>>(k_c, kT16, TT, RANK);
    }

    // 1) qf = q @ wq^T : fp16 1-term; fp32 qf + fp16 hi (qc2 layout)
    gemm_f16<<<dim3(QFW / 128, TT / 128, 1), 256, 3 * 2 * PART>>>(
        q16, q16, wq16, qf, qf16,
        QIN, QIN, QIN, QFW, 0, 0, 0, 1.0f, 0, 0, 1);

    // 2) rope + pack
    rope_pack<<<TT, 256>>>(qf, k_pe, pos, cosc, sinc);

    // 3) k_up_h = k_c @ w_uk_h : fp16 1-term, hi out -> kc2f[:,0:128]
    gemm_f16<<<dim3(1, TT / 128, H), 256, 3 * 2 * PART>>>(
        kc16, kc16, kvb16, nullptr, kc2f,
        RANK, RANK, RANK, DS,
        0, (long long)256 * RANK, (long long)TT * DS, 1.0f, 0, 0, 1);

    // 4) S_h = Qf16_h @ Kc2f_h^T : fp16 1-term, K=192, causal skip, hi out
    gemm_f16<<<dim3(TT / 128, TT / 128, H), 256, 3 * 2 * PART>>>(
        qf16, qf16, kc2f, nullptr, Sp_h,
        DS, QFW, DS, TT,
        (long long)DS, (long long)TT * DS, (long long)TT * TT, 1.0f, 1, 0, 1);

    // 5) softmax in-place (scale on load)
    softmax_causal<<<dim3(TT, H), 256>>>(Sp_h, pos, scale);

    // 6) olat_h = P_h @ k_c : fp16 1-term, K limited to m0+128, hi out
    gemm_f16<<<dim3(RANK / 128, TT / 128, H), 256, 3 * 2 * PART>>>(
        Sp_h, Sp_h, kT16, nullptr, ol16,
        TT, TT, TT, H * RANK,
        (long long)TT * TT, 0, (long long)RANK, 1.0f, 2, 0, 1);

    // 7) o_h = olat_h @ w_uv_h : fp16 1-term, hi out
    gemm_f16<<<dim3(VDIM / 128, TT / 128, H), 256, 3 * 2 * PART>>>(
        ol16, ol16, kvb16 + (long long)NOPE * RANK, nullptr, o_h,
        RANK, H * RANK, RANK, H * VDIM,
        (long long)RANK, (long long)256 * RANK, (long long)VDIM, 1.0f, 0, 0, 1);

    // 8) out = o @ wo^T : fp16 1-term, fp32 out
    gemm_f16<<<dim3(HID / 128, TT / 128, 1), 256, 3 * 2 * PART>>>(
        o_h, o_h, wo16, out, nullptr,
        H * VDIM, H * VDIM, H * VDIM, HID, 0, 0, 0, 1.0f, 0, 0, 0);
}